// round 1
// baseline (speedup 1.0000x reference)
#include <cuda_runtime.h>
#include <cuda_bf16.h>
#include <math.h>

// Problem dims
#define B_   2
#define T_   1024
#define D_   1024
#define DI_  2048          // D_INNER
#define DS_  16            // D_STATE
#define DC_  4             // D_CONV
#define R_   64            // DT_RANK
#define XDBC_ 96           // R_ + 2*DS_
#define MROWS (B_*T_)      // 2048

// Scratch (device globals; no allocation allowed)
__device__ float g_xn[MROWS * D_];            // 8 MB
__device__ float g_xz[MROWS * 2 * DI_];       // 32 MB
__device__ float g_u[MROWS * DI_];            // 16 MB
__device__ float g_xdbc[MROWS * XDBC_];       // 0.75 MB
__device__ float g_delta[MROWS * DI_];        // 16 MB
__device__ float g_y[MROWS * DI_];            // 16 MB

// ---------------------------------------------------------------------------
// RMSNorm: one block per row of 1024
// ---------------------------------------------------------------------------
__global__ void rmsnorm_kernel(const float* __restrict__ x,
                               const float* __restrict__ w,
                               float* __restrict__ o)
{
    int row = blockIdx.x;
    const float* xr = x + (size_t)row * D_;
    float s = 0.f;
    for (int i = threadIdx.x; i < D_; i += 256) {
        float v = xr[i];
        s += v * v;
    }
    __shared__ float red[8];
    for (int off = 16; off; off >>= 1) s += __shfl_xor_sync(0xffffffffu, s, off);
    if ((threadIdx.x & 31) == 0) red[threadIdx.x >> 5] = s;
    __syncthreads();
    if (threadIdx.x < 8) {
        float t = red[threadIdx.x];
        t += __shfl_xor_sync(0xffu, t, 4);
        t += __shfl_xor_sync(0xffu, t, 2);
        t += __shfl_xor_sync(0xffu, t, 1);
        if (threadIdx.x == 0) red[0] = t;
    }
    __syncthreads();
    float scale = rsqrtf(red[0] * (1.f / D_) + 1.1920929e-7f);
    float* orow = o + (size_t)row * D_;
    for (int i = threadIdx.x; i < D_; i += 256)
        orow[i] = xr[i] * scale * w[i];
}

// ---------------------------------------------------------------------------
// Generic tiled f32 GEMM:  C[M,N] = A[M,K(lda)] @ W[N,K]^T  (+ epilogue)
// BM=BN=64, BK=16, 256 threads, 4x4 microtile.
// EPI: 0 = plain, 1 = softplus(v + bias[n]), 2 = v + res[m*N+n]
// ---------------------------------------------------------------------------
template<int EPI>
__global__ void gemm64_kernel(const float* __restrict__ A, int lda,
                              const float* __restrict__ W,
                              const float* __restrict__ bias,
                              const float* __restrict__ res,
                              float* __restrict__ C,
                              int M, int N, int K)
{
    __shared__ float As[16][68];   // stride 68 keeps float4 alignment, reduces conflicts
    __shared__ float Ws[16][68];

    int tid = threadIdx.x;          // 0..255
    int tx = tid & 15;
    int ty = tid >> 4;
    int m0 = blockIdx.y * 64;
    int n0 = blockIdx.x * 64;

    int lr = tid >> 4;              // 0..15 (row base for tile loads)
    int lc = tid & 15;              // k index within BK

    float acc[4][4];
#pragma unroll
    for (int i = 0; i < 4; i++)
#pragma unroll
        for (int j = 0; j < 4; j++) acc[i][j] = 0.f;

    for (int k0 = 0; k0 < K; k0 += 16) {
#pragma unroll
        for (int it = 0; it < 4; it++) {
            int r = lr + it * 16;
            As[lc][r] = A[(size_t)(m0 + r) * lda + k0 + lc];
            int wn = n0 + r;
            Ws[lc][r] = (wn < N) ? W[(size_t)wn * K + k0 + lc] : 0.f;
        }
        __syncthreads();
#pragma unroll
        for (int kk = 0; kk < 16; kk++) {
            float4 av = *(const float4*)&As[kk][ty * 4];
            float4 bv = *(const float4*)&Ws[kk][tx * 4];
            float a[4] = {av.x, av.y, av.z, av.w};
            float b[4] = {bv.x, bv.y, bv.z, bv.w};
#pragma unroll
            for (int i = 0; i < 4; i++)
#pragma unroll
                for (int j = 0; j < 4; j++)
                    acc[i][j] += a[i] * b[j];
        }
        __syncthreads();
    }

#pragma unroll
    for (int i = 0; i < 4; i++) {
        int m = m0 + ty * 4 + i;
#pragma unroll
        for (int j = 0; j < 4; j++) {
            int n = n0 + tx * 4 + j;
            if (n < N) {
                float v = acc[i][j];
                if (EPI == 1) {
                    v += bias[n];
                    v = (v > 20.f) ? v : log1pf(__expf(v));
                }
                if (EPI == 2) {
                    v += res[(size_t)m * N + n];
                }
                C[(size_t)m * N + n] = v;
            }
        }
    }
}

// ---------------------------------------------------------------------------
// Depthwise causal conv (width 4) + bias + SiLU.  Input = first half of xz.
// ---------------------------------------------------------------------------
__global__ void conv_silu_kernel(const float* __restrict__ xz,
                                 const float* __restrict__ cw,
                                 const float* __restrict__ cb,
                                 float* __restrict__ u)
{
    int idx = blockIdx.x * blockDim.x + threadIdx.x;   // over B*T*DI
    if (idx >= MROWS * DI_) return;
    int i  = idx % DI_;
    int bt = idx / DI_;
    int t  = bt % T_;
    float acc = cb[i];
    float w0 = cw[i * 4 + 0], w1 = cw[i * 4 + 1], w2 = cw[i * 4 + 2], w3 = cw[i * 4 + 3];
    if (t >= 3) acc += w0 * xz[(size_t)(bt - 3) * (2 * DI_) + i];
    if (t >= 2) acc += w1 * xz[(size_t)(bt - 2) * (2 * DI_) + i];
    if (t >= 1) acc += w2 * xz[(size_t)(bt - 1) * (2 * DI_) + i];
    acc += w3 * xz[(size_t)bt * (2 * DI_) + i];
    float sg = 1.f / (1.f + __expf(-acc));
    u[idx] = acc * sg;
}

// ---------------------------------------------------------------------------
// Selective scan. Warp = 2 channels x 16 states; lane s holds h[s] for its
// channel. Sequential over T with next-step loads prefetched. Fuses the
// +u*D and *silu(z) epilogue on lane 0.
// grid = B * DI/16 = 256 blocks, 256 threads.
// ---------------------------------------------------------------------------
__global__ void scan_kernel(const float* __restrict__ delta,
                            const float* __restrict__ u,
                            const float* __restrict__ xdbc,
                            const float* __restrict__ xz,
                            const float* __restrict__ A_log,
                            const float* __restrict__ Dp,
                            float* __restrict__ y)
{
    int b = blockIdx.x >> 7;                               // DI/16 = 128 blocks per batch
    int i = ((blockIdx.x & 127) << 4) + (threadIdx.x >> 4);
    int s = threadIdx.x & 15;

    float a  = -__expf(A_log[i * DS_ + s]);
    float dp = Dp[i];
    float h  = 0.f;

    int rt = b * T_;
    float d  = delta[(size_t)rt * DI_ + i];
    float uu = u[(size_t)rt * DI_ + i];
    float Bv = xdbc[(size_t)rt * XDBC_ + R_ + s];
    float Cv = xdbc[(size_t)rt * XDBC_ + R_ + DS_ + s];

    for (int t = 0; t < T_; t++) {
        int rtn = rt + 1;
        float d2 = 0.f, uu2 = 0.f, Bv2 = 0.f, Cv2 = 0.f;
        if (t + 1 < T_) {
            d2  = delta[(size_t)rtn * DI_ + i];
            uu2 = u[(size_t)rtn * DI_ + i];
            Bv2 = xdbc[(size_t)rtn * XDBC_ + R_ + s];
            Cv2 = xdbc[(size_t)rtn * XDBC_ + R_ + DS_ + s];
        }

        h = __expf(d * a) * h + (d * uu) * Bv;
        float p = h * Cv;
        p += __shfl_xor_sync(0xffffffffu, p, 8, 16);
        p += __shfl_xor_sync(0xffffffffu, p, 4, 16);
        p += __shfl_xor_sync(0xffffffffu, p, 2, 16);
        p += __shfl_xor_sync(0xffffffffu, p, 1, 16);

        if (s == 0) {
            float z  = xz[(size_t)rt * (2 * DI_) + DI_ + i];
            float yv = (p + uu * dp) * (z / (1.f + __expf(-z)));
            y[(size_t)rt * DI_ + i] = yv;
        }

        d = d2; uu = uu2; Bv = Bv2; Cv = Cv2; rt = rtn;
    }
}

// ---------------------------------------------------------------------------
// Launch
// ---------------------------------------------------------------------------
extern "C" void kernel_launch(void* const* d_in, const int* in_sizes, int n_in,
                              void* d_out, int out_size)
{
    const float* x          = (const float*)d_in[0];
    const float* norm_w     = (const float*)d_in[1];
    const float* in_proj_w  = (const float*)d_in[2];
    const float* conv_w     = (const float*)d_in[3];
    const float* conv_b     = (const float*)d_in[4];
    const float* x_proj_w   = (const float*)d_in[5];
    const float* dt_proj_w  = (const float*)d_in[6];
    const float* dt_proj_b  = (const float*)d_in[7];
    const float* A_log      = (const float*)d_in[8];
    const float* D_param    = (const float*)d_in[9];
    const float* out_proj_w = (const float*)d_in[10];
    float* out = (float*)d_out;

    float *xn, *xz, *u, *xdbc, *delta, *y;
    cudaGetSymbolAddress((void**)&xn,    g_xn);
    cudaGetSymbolAddress((void**)&xz,    g_xz);
    cudaGetSymbolAddress((void**)&u,     g_u);
    cudaGetSymbolAddress((void**)&xdbc,  g_xdbc);
    cudaGetSymbolAddress((void**)&delta, g_delta);
    cudaGetSymbolAddress((void**)&y,     g_y);

    // 1. RMSNorm
    rmsnorm_kernel<<<MROWS, 256>>>(x, norm_w, xn);

    // 2. in_proj: xz[2048,4096] = xn[2048,1024] @ in_proj_w[4096,1024]^T
    gemm64_kernel<0><<<dim3(4096 / 64, MROWS / 64), 256>>>(
        xn, D_, in_proj_w, nullptr, nullptr, xz, MROWS, 2 * DI_, D_);

    // 3. conv + silu -> u
    conv_silu_kernel<<<(MROWS * DI_ + 255) / 256, 256>>>(xz, conv_w, conv_b, u);

    // 4. x_proj: xdbc[2048,96] = u @ x_proj_w[96,2048]^T
    gemm64_kernel<0><<<dim3(2, MROWS / 64), 256>>>(
        u, DI_, x_proj_w, nullptr, nullptr, xdbc, MROWS, XDBC_, DI_);

    // 5. dt_proj + softplus: delta[2048,2048] = softplus(xdbc[:, :64] @ dt_proj_w^T + b)
    gemm64_kernel<1><<<dim3(DI_ / 64, MROWS / 64), 256>>>(
        xdbc, XDBC_, dt_proj_w, dt_proj_b, nullptr, delta, MROWS, DI_, R_);

    // 6. selective scan (fused gate + skip)
    scan_kernel<<<B_ * (DI_ / 16), 256>>>(delta, u, xdbc, xz, A_log, D_param, y);

    // 7. out_proj + residual
    gemm64_kernel<2><<<dim3(D_ / 64, MROWS / 64), 256>>>(
        y, DI_, out_proj_w, nullptr, x, out, MROWS, D_, DI_);
}

// round 3
// speedup vs baseline: 1.5887x; 1.5887x over previous
#include <cuda_runtime.h>
#include <cuda_bf16.h>
#include <math.h>
#include <stdint.h>

// Problem dims
#define B_   2
#define T_   1024
#define D_   1024
#define DI_  2048          // D_INNER
#define DS_  16            // D_STATE
#define R_   64            // DT_RANK
#define XDBC_ 96           // R_ + 2*DS_
#define MROWS (B_*T_)      // 2048

// ---------------------------------------------------------------------------
// Scratch (device globals; no allocation allowed)
// ---------------------------------------------------------------------------
__device__ __align__(256) float g_xz[MROWS * 2 * DI_];
__device__ __align__(256) float g_u[MROWS * DI_];
__device__ __align__(256) float g_xdbc[MROWS * XDBC_];
__device__ __align__(256) float g_delta[MROWS * DI_];

__device__ __align__(256) __nv_bfloat16 g_xn_h[MROWS * D_];
__device__ __align__(256) __nv_bfloat16 g_xn_l[MROWS * D_];
__device__ __align__(256) __nv_bfloat16 g_u_h[MROWS * DI_];
__device__ __align__(256) __nv_bfloat16 g_u_l[MROWS * DI_];
__device__ __align__(256) __nv_bfloat16 g_y_h[MROWS * DI_];
__device__ __align__(256) __nv_bfloat16 g_y_l[MROWS * DI_];
__device__ __align__(256) __nv_bfloat16 g_xdbc_h[MROWS * XDBC_];
__device__ __align__(256) __nv_bfloat16 g_xdbc_l[MROWS * XDBC_];
__device__ __align__(256) __nv_bfloat16 g_win_h[2 * DI_ * D_];
__device__ __align__(256) __nv_bfloat16 g_win_l[2 * DI_ * D_];
__device__ __align__(256) __nv_bfloat16 g_wout_h[D_ * DI_];
__device__ __align__(256) __nv_bfloat16 g_wout_l[D_ * DI_];
__device__ __align__(256) __nv_bfloat16 g_wxp_h[XDBC_ * DI_];
__device__ __align__(256) __nv_bfloat16 g_wxp_l[XDBC_ * DI_];
__device__ __align__(256) __nv_bfloat16 g_wdt_h[DI_ * R_];
__device__ __align__(256) __nv_bfloat16 g_wdt_l[DI_ * R_];

// ---------------------------------------------------------------------------
// Helpers
// ---------------------------------------------------------------------------
__device__ __forceinline__ uint32_t smem_u32(const void* p) {
    uint32_t a;
    asm("{ .reg .u64 t; cvta.to.shared.u64 t, %1; cvt.u32.u64 %0, t; }" : "=r"(a) : "l"(p));
    return a;
}
// swizzle for 64-byte rows: c' = c ^ ((r>>1)&3) on 16B chunks
__device__ __forceinline__ uint32_t sw64(uint32_t b) { return b ^ ((b >> 3) & 0x30); }

__device__ __forceinline__ void cp16(uint32_t smem, const void* gmem, int srcBytes) {
    asm volatile("cp.async.cg.shared.global [%0], [%1], 16, %2;"
                 :: "r"(smem), "l"(gmem), "r"(srcBytes));
}
__device__ __forceinline__ void cp_commit() {
    asm volatile("cp.async.commit_group;" ::: "memory");
}
template<int N>
__device__ __forceinline__ void cp_wait() {
    asm volatile("cp.async.wait_group %0;" :: "n"(N) : "memory");
}

__device__ __forceinline__ void ldsm_x4(uint32_t* r, uint32_t addr) {
    asm volatile("ldmatrix.sync.aligned.m8n8.x4.shared.b16 {%0,%1,%2,%3}, [%4];"
                 : "=r"(r[0]), "=r"(r[1]), "=r"(r[2]), "=r"(r[3]) : "r"(addr));
}
__device__ __forceinline__ void ldsm_x2(uint32_t* r, uint32_t addr) {
    asm volatile("ldmatrix.sync.aligned.m8n8.x2.shared.b16 {%0,%1}, [%2];"
                 : "=r"(r[0]), "=r"(r[1]) : "r"(addr));
}
__device__ __forceinline__ void mma16816(float* c, const uint32_t* a, const uint32_t* b) {
    asm volatile("mma.sync.aligned.m16n8k16.row.col.f32.bf16.bf16.f32 "
                 "{%0,%1,%2,%3}, {%4,%5,%6,%7}, {%8,%9}, {%0,%1,%2,%3};"
                 : "+f"(c[0]), "+f"(c[1]), "+f"(c[2]), "+f"(c[3])
                 : "r"(a[0]), "r"(a[1]), "r"(a[2]), "r"(a[3]), "r"(b[0]), "r"(b[1]));
}

__device__ __forceinline__ void split_f32(float v, __nv_bfloat16& h, __nv_bfloat16& l) {
    h = __float2bfloat16(v);
    l = __float2bfloat16(v - __bfloat162float(h));
}

__global__ void split_kernel(const float* __restrict__ src,
                             __nv_bfloat16* __restrict__ hi,
                             __nv_bfloat16* __restrict__ lo, int n)
{
    int i = blockIdx.x * blockDim.x + threadIdx.x;
    if (i < n) { __nv_bfloat16 h, l; split_f32(src[i], h, l); hi[i] = h; lo[i] = l; }
}

// ---------------------------------------------------------------------------
// RMSNorm -> hi/lo bf16
// ---------------------------------------------------------------------------
__global__ void rmsnorm_kernel(const float* __restrict__ x,
                               const float* __restrict__ w,
                               __nv_bfloat16* __restrict__ oh,
                               __nv_bfloat16* __restrict__ ol)
{
    int row = blockIdx.x;
    const float* xr = x + (size_t)row * D_;
    float s = 0.f;
    for (int i = threadIdx.x; i < D_; i += 256) { float v = xr[i]; s += v * v; }
    __shared__ float red[8];
    for (int off = 16; off; off >>= 1) s += __shfl_xor_sync(0xffffffffu, s, off);
    if ((threadIdx.x & 31) == 0) red[threadIdx.x >> 5] = s;
    __syncthreads();
    if (threadIdx.x < 8) {
        float t = red[threadIdx.x];
        t += __shfl_xor_sync(0xffu, t, 4);
        t += __shfl_xor_sync(0xffu, t, 2);
        t += __shfl_xor_sync(0xffu, t, 1);
        if (threadIdx.x == 0) red[0] = t;
    }
    __syncthreads();
    float scale = rsqrtf(red[0] * (1.f / D_) + 1.1920929e-7f);
    for (int i = threadIdx.x; i < D_; i += 256) {
        __nv_bfloat16 h, l; split_f32(xr[i] * scale * w[i], h, l);
        oh[(size_t)row * D_ + i] = h;
        ol[(size_t)row * D_ + i] = l;
    }
}

// ---------------------------------------------------------------------------
// Tensor-core GEMM via mma.sync (bf16 hi/lo = emulated fp32):
//   C[M, N(ldc)] (op)= A[M, *](lda) @ W[N, *](ldb)^T over K range [kStart, kStart+kLen)
// 128x128 CTA tile, BK=32, 8 warps (2x4), warp tile 64x32, double-buffered cp.async.
// EPI: 0 = store, 1 = atomicAdd (split-K), 2 = store + res, 3 = softplus(v + bias[n])
// Dyn smem: 2 stages x 32KB (Ah 8K | Al 8K | Bh 8K | Bl 8K)
// ---------------------------------------------------------------------------
#define GSTAGE 32768

template<int EPI>
__global__ void __launch_bounds__(256)
gemm_tc_kernel(const __nv_bfloat16* __restrict__ Ah, const __nv_bfloat16* __restrict__ Al, int lda,
               const __nv_bfloat16* __restrict__ Bh, const __nv_bfloat16* __restrict__ Bl, int ldb,
               const float* __restrict__ aux, float* __restrict__ C,
               int N, int ldc, int kLen)
{
    extern __shared__ char smem[];
    uint32_t sb = smem_u32(smem);
    int tid = threadIdx.x, wid = tid >> 5, lid = tid & 31;
    int m0 = blockIdx.y * 128, n0 = blockIdx.x * 128;
    int kStart = blockIdx.z * kLen;
    int bRows = N - n0; if (bRows > 128) bRows = 128;
    int wm = (wid >> 2) * 64, wn = (wid & 3) * 32;

    float acc[4][4][4];
#pragma unroll
    for (int i = 0; i < 4; i++)
#pragma unroll
        for (int j = 0; j < 4; j++)
#pragma unroll
            for (int k = 0; k < 4; k++) acc[i][j][k] = 0.f;

    int nCh = kLen / 32;

    // chunk loader: stage s, k-offset k0
    auto load_chunk = [&](int s, int k0) {
        uint32_t st = sb + s * GSTAGE;
#pragma unroll
        for (int p = 0; p < 2; p++) {
            int idx = tid + p * 256;          // 0..511
            int r = idx >> 2, c = idx & 3;    // row, 16B-chunk
            uint32_t so = sw64((uint32_t)(r * 64 + c * 16));
            const __nv_bfloat16* ga = Ah + (size_t)(m0 + r) * lda + k0 + c * 8;
            const __nv_bfloat16* gal = Al + (size_t)(m0 + r) * lda + k0 + c * 8;
            cp16(st + so, ga, 16);
            cp16(st + 8192 + so, gal, 16);
            int rb = (r < bRows) ? r : (bRows - 1);
            int ok = (r < bRows) ? 16 : 0;
            const __nv_bfloat16* gb = Bh + (size_t)(n0 + rb) * ldb + k0 + c * 8;
            const __nv_bfloat16* gbl = Bl + (size_t)(n0 + rb) * ldb + k0 + c * 8;
            cp16(st + 16384 + so, gb, ok);
            cp16(st + 24576 + so, gbl, ok);
        }
        cp_commit();
    };

    load_chunk(0, kStart);

    for (int ch = 0; ch < nCh; ch++) {
        bool hasNext = (ch + 1 < nCh);
        if (hasNext) load_chunk((ch + 1) & 1, kStart + (ch + 1) * 32);
        if (hasNext) cp_wait<1>(); else cp_wait<0>();
        __syncthreads();

        uint32_t st = sb + (ch & 1) * GSTAGE;
#pragma unroll
        for (int ks = 0; ks < 2; ks++) {
            uint32_t ah[4][4], al[4][4], bh[4][2], bl[4][2];
#pragma unroll
            for (int mt = 0; mt < 4; mt++) {
                int row = wm + mt * 16 + (lid & 15);
                int kk = ks * 16 + (lid >> 4) * 8;
                uint32_t so = sw64((uint32_t)(row * 64 + kk * 2));
                ldsm_x4(ah[mt], st + so);
                ldsm_x4(al[mt], st + 8192 + so);
            }
#pragma unroll
            for (int nt = 0; nt < 4; nt++) {
                int row = wn + nt * 8 + (lid & 7);
                int kk = ks * 16 + ((lid >> 3) & 1) * 8;
                uint32_t so = sw64((uint32_t)(row * 64 + kk * 2));
                ldsm_x2(bh[nt], st + 16384 + so);
                ldsm_x2(bl[nt], st + 24576 + so);
            }
#pragma unroll
            for (int mt = 0; mt < 4; mt++)
#pragma unroll
                for (int nt = 0; nt < 4; nt++) {
                    mma16816(acc[mt][nt], ah[mt], bh[nt]);
                    mma16816(acc[mt][nt], ah[mt], bl[nt]);
                    mma16816(acc[mt][nt], al[mt], bh[nt]);
                }
        }
        __syncthreads();
    }

    // Epilogue
    int gid = lid >> 2, tig = lid & 3;
#pragma unroll
    for (int mt = 0; mt < 4; mt++) {
        int r0 = m0 + wm + mt * 16 + gid;
#pragma unroll
        for (int nt = 0; nt < 4; nt++) {
            int cc = n0 + wn + nt * 8 + tig * 2;
            float* a = acc[mt][nt];
#pragma unroll
            for (int half = 0; half < 2; half++) {
                int r = r0 + half * 8;
                float v0 = a[half * 2 + 0], v1 = a[half * 2 + 1];
                size_t o = (size_t)r * ldc + cc;
                if (EPI == 0) {
                    *(float2*)&C[o] = make_float2(v0, v1);
                } else if (EPI == 1) {
                    if (cc < N) { atomicAdd(&C[o], v0); atomicAdd(&C[o + 1], v1); }
                } else if (EPI == 2) {
                    float2 rr = *(const float2*)&aux[o];
                    *(float2*)&C[o] = make_float2(v0 + rr.x, v1 + rr.y);
                } else {
                    float b0 = aux[cc], b1 = aux[cc + 1];
                    float s0 = v0 + b0, s1 = v1 + b1;
                    s0 = (s0 > 20.f) ? s0 : log1pf(__expf(s0));
                    s1 = (s1 > 20.f) ? s1 : log1pf(__expf(s1));
                    *(float2*)&C[o] = make_float2(s0, s1);
                }
            }
        }
    }
}

// ---------------------------------------------------------------------------
// Depthwise causal conv (width 4) + bias + SiLU -> u (f32) + hi/lo bf16
// ---------------------------------------------------------------------------
__global__ void conv_silu_kernel(const float* __restrict__ xz,
                                 const float* __restrict__ cw,
                                 const float* __restrict__ cb,
                                 float* __restrict__ u,
                                 __nv_bfloat16* __restrict__ uh,
                                 __nv_bfloat16* __restrict__ ul)
{
    int idx = blockIdx.x * blockDim.x + threadIdx.x;
    if (idx >= MROWS * DI_) return;
    int i = idx % DI_;
    int bt = idx / DI_;
    int t = bt % T_;
    float acc = cb[i];
    float w0 = cw[i * 4 + 0], w1 = cw[i * 4 + 1], w2 = cw[i * 4 + 2], w3 = cw[i * 4 + 3];
    if (t >= 3) acc += w0 * xz[(size_t)(bt - 3) * (2 * DI_) + i];
    if (t >= 2) acc += w1 * xz[(size_t)(bt - 2) * (2 * DI_) + i];
    if (t >= 1) acc += w2 * xz[(size_t)(bt - 1) * (2 * DI_) + i];
    acc += w3 * xz[(size_t)bt * (2 * DI_) + i];
    float v = acc / (1.f + __expf(-acc));
    u[idx] = v;
    __nv_bfloat16 h, l; split_f32(v, h, l);
    uh[idx] = h; ul[idx] = l;
}

// ---------------------------------------------------------------------------
// Selective scan. Warp = 2 channels x 16 states. Outputs y as hi/lo bf16.
// ---------------------------------------------------------------------------
__global__ void scan_kernel(const float* __restrict__ delta,
                            const float* __restrict__ u,
                            const float* __restrict__ xdbc,
                            const float* __restrict__ xz,
                            const float* __restrict__ A_log,
                            const float* __restrict__ Dp,
                            __nv_bfloat16* __restrict__ yh,
                            __nv_bfloat16* __restrict__ yl)
{
    int b = blockIdx.x >> 7;
    int i = ((blockIdx.x & 127) << 4) + (threadIdx.x >> 4);
    int s = threadIdx.x & 15;

    float a = -__expf(A_log[i * DS_ + s]);
    float dp = Dp[i];
    float h = 0.f;

    int rt = b * T_;
    float d  = delta[(size_t)rt * DI_ + i];
    float uu = u[(size_t)rt * DI_ + i];
    float Bv = xdbc[(size_t)rt * XDBC_ + R_ + s];
    float Cv = xdbc[(size_t)rt * XDBC_ + R_ + DS_ + s];

    for (int t = 0; t < T_; t++) {
        int rtn = rt + 1;
        float d2 = 0.f, uu2 = 0.f, Bv2 = 0.f, Cv2 = 0.f;
        if (t + 1 < T_) {
            d2  = delta[(size_t)rtn * DI_ + i];
            uu2 = u[(size_t)rtn * DI_ + i];
            Bv2 = xdbc[(size_t)rtn * XDBC_ + R_ + s];
            Cv2 = xdbc[(size_t)rtn * XDBC_ + R_ + DS_ + s];
        }

        h = __expf(d * a) * h + (d * uu) * Bv;
        float p = h * Cv;
        p += __shfl_xor_sync(0xffffffffu, p, 8, 16);
        p += __shfl_xor_sync(0xffffffffu, p, 4, 16);
        p += __shfl_xor_sync(0xffffffffu, p, 2, 16);
        p += __shfl_xor_sync(0xffffffffu, p, 1, 16);

        if (s == 0) {
            float z = xz[(size_t)rt * (2 * DI_) + DI_ + i];
            float yv = (p + uu * dp) * (z / (1.f + __expf(-z)));
            __nv_bfloat16 hh, ll; split_f32(yv, hh, ll);
            yh[(size_t)rt * DI_ + i] = hh;
            yl[(size_t)rt * DI_ + i] = ll;
        }
        d = d2; uu = uu2; Bv = Bv2; Cv = Cv2; rt = rtn;
    }
}

// ---------------------------------------------------------------------------
// Launch
// ---------------------------------------------------------------------------
extern "C" void kernel_launch(void* const* d_in, const int* in_sizes, int n_in,
                              void* d_out, int out_size)
{
    const float* x          = (const float*)d_in[0];
    const float* norm_w     = (const float*)d_in[1];
    const float* in_proj_w  = (const float*)d_in[2];
    const float* conv_w     = (const float*)d_in[3];
    const float* conv_b     = (const float*)d_in[4];
    const float* x_proj_w   = (const float*)d_in[5];
    const float* dt_proj_w  = (const float*)d_in[6];
    const float* dt_proj_b  = (const float*)d_in[7];
    const float* A_log      = (const float*)d_in[8];
    const float* D_param    = (const float*)d_in[9];
    const float* out_proj_w = (const float*)d_in[10];
    float* out = (float*)d_out;

    float *xz, *u, *xdbc, *delta;
    __nv_bfloat16 *xnh, *xnl, *uh, *ul, *yh, *yl, *xdh, *xdl;
    __nv_bfloat16 *winh, *winl, *wouth, *woutl, *wxph, *wxpl, *wdth, *wdtl;
    cudaGetSymbolAddress((void**)&xz,    g_xz);
    cudaGetSymbolAddress((void**)&u,     g_u);
    cudaGetSymbolAddress((void**)&xdbc,  g_xdbc);
    cudaGetSymbolAddress((void**)&delta, g_delta);
    cudaGetSymbolAddress((void**)&xnh,   g_xn_h);
    cudaGetSymbolAddress((void**)&xnl,   g_xn_l);
    cudaGetSymbolAddress((void**)&uh,    g_u_h);
    cudaGetSymbolAddress((void**)&ul,    g_u_l);
    cudaGetSymbolAddress((void**)&yh,    g_y_h);
    cudaGetSymbolAddress((void**)&yl,    g_y_l);
    cudaGetSymbolAddress((void**)&xdh,   g_xdbc_h);
    cudaGetSymbolAddress((void**)&xdl,   g_xdbc_l);
    cudaGetSymbolAddress((void**)&winh,  g_win_h);
    cudaGetSymbolAddress((void**)&winl,  g_win_l);
    cudaGetSymbolAddress((void**)&wouth, g_wout_h);
    cudaGetSymbolAddress((void**)&woutl, g_wout_l);
    cudaGetSymbolAddress((void**)&wxph,  g_wxp_h);
    cudaGetSymbolAddress((void**)&wxpl,  g_wxp_l);
    cudaGetSymbolAddress((void**)&wdth,  g_wdt_h);
    cudaGetSymbolAddress((void**)&wdtl,  g_wdt_l);

    int smem = 2 * GSTAGE;
    cudaFuncSetAttribute(gemm_tc_kernel<0>, cudaFuncAttributeMaxDynamicSharedMemorySize, smem);
    cudaFuncSetAttribute(gemm_tc_kernel<1>, cudaFuncAttributeMaxDynamicSharedMemorySize, smem);
    cudaFuncSetAttribute(gemm_tc_kernel<2>, cudaFuncAttributeMaxDynamicSharedMemorySize, smem);
    cudaFuncSetAttribute(gemm_tc_kernel<3>, cudaFuncAttributeMaxDynamicSharedMemorySize, smem);

    // 0. Split weights into bf16 hi/lo
    split_kernel<<<(2 * DI_ * D_ + 255) / 256, 256>>>(in_proj_w, winh, winl, 2 * DI_ * D_);
    split_kernel<<<(D_ * DI_ + 255) / 256, 256>>>(out_proj_w, wouth, woutl, D_ * DI_);
    split_kernel<<<(XDBC_ * DI_ + 255) / 256, 256>>>(x_proj_w, wxph, wxpl, XDBC_ * DI_);
    split_kernel<<<(DI_ * R_ + 255) / 256, 256>>>(dt_proj_w, wdth, wdtl, DI_ * R_);

    // 1. RMSNorm -> xn hi/lo
    rmsnorm_kernel<<<MROWS, 256>>>(x, norm_w, xnh, xnl);

    // 2. in_proj: xz[2048,4096] = xn @ W^T
    gemm_tc_kernel<0><<<dim3(2 * DI_ / 128, MROWS / 128, 1), 256, smem>>>(
        xnh, xnl, D_, winh, winl, D_, nullptr, xz, 2 * DI_, 2 * DI_, D_);

    // 3. conv + silu -> u (f32 + hi/lo)
    conv_silu_kernel<<<(MROWS * DI_ + 255) / 256, 256>>>(xz, conv_w, conv_b, u, uh, ul);

    // 4. x_proj: xdbc[2048,96] = u @ W^T (split-K=8, atomics)
    cudaMemsetAsync(xdbc, 0, (size_t)MROWS * XDBC_ * sizeof(float));
    gemm_tc_kernel<1><<<dim3(1, MROWS / 128, 8), 256, smem>>>(
        uh, ul, DI_, wxph, wxpl, DI_, nullptr, xdbc, XDBC_, XDBC_, DI_ / 8);

    // 4b. split xdbc -> bf16 hi/lo (for dt_proj)
    split_kernel<<<(MROWS * XDBC_ + 255) / 256, 256>>>(xdbc, xdh, xdl, MROWS * XDBC_);

    // 5. dt_proj + softplus: delta[2048,2048]
    gemm_tc_kernel<3><<<dim3(DI_ / 128, MROWS / 128, 1), 256, smem>>>(
        xdh, xdl, XDBC_, wdth, wdtl, R_, dt_proj_b, delta, DI_, DI_, R_);

    // 6. selective scan -> y hi/lo (fused gate + skip)
    scan_kernel<<<B_ * (DI_ / 16), 256>>>(delta, u, xdbc, xz, A_log, D_param, yh, yl);

    // 7. out_proj + residual
    gemm_tc_kernel<2><<<dim3(D_ / 128, MROWS / 128, 1), 256, smem>>>(
        yh, yl, DI_, wouth, woutl, DI_, x, out, D_, D_, DI_);
}

// round 5
// speedup vs baseline: 3.0151x; 1.8979x over previous
#include <cuda_runtime.h>
#include <cuda_bf16.h>
#include <math.h>
#include <stdint.h>

// Problem dims
#define B_   2
#define T_   1024
#define D_   1024
#define DI_  2048          // D_INNER
#define DS_  16            // D_STATE
#define R_   64            // DT_RANK
#define XDBC_ 96           // R_ + 2*DS_
#define MROWS (B_*T_)      // 2048

// ---------------------------------------------------------------------------
// Scratch (device globals; no allocation allowed)
// ---------------------------------------------------------------------------
__device__ __align__(256) float g_xz[MROWS * 2 * DI_];
__device__ __align__(256) float g_u[MROWS * DI_];
__device__ __align__(256) float g_xdbc[MROWS * XDBC_];
__device__ __align__(256) float g_delta[MROWS * DI_];

__device__ __align__(256) __nv_bfloat16 g_xn_h[MROWS * D_];
__device__ __align__(256) __nv_bfloat16 g_xn_l[MROWS * D_];
__device__ __align__(256) __nv_bfloat16 g_u_h[MROWS * DI_];
__device__ __align__(256) __nv_bfloat16 g_u_l[MROWS * DI_];
__device__ __align__(256) __nv_bfloat16 g_y_h[MROWS * DI_];
__device__ __align__(256) __nv_bfloat16 g_y_l[MROWS * DI_];
__device__ __align__(256) __nv_bfloat16 g_xdbc_h[MROWS * XDBC_];
__device__ __align__(256) __nv_bfloat16 g_xdbc_l[MROWS * XDBC_];
__device__ __align__(256) __nv_bfloat16 g_win_h[2 * DI_ * D_];
__device__ __align__(256) __nv_bfloat16 g_win_l[2 * DI_ * D_];
__device__ __align__(256) __nv_bfloat16 g_wout_h[D_ * DI_];
__device__ __align__(256) __nv_bfloat16 g_wout_l[D_ * DI_];
__device__ __align__(256) __nv_bfloat16 g_wxp_h[XDBC_ * DI_];
__device__ __align__(256) __nv_bfloat16 g_wxp_l[XDBC_ * DI_];
__device__ __align__(256) __nv_bfloat16 g_wdt_h[DI_ * R_];
__device__ __align__(256) __nv_bfloat16 g_wdt_l[DI_ * R_];

// ---------------------------------------------------------------------------
// Helpers
// ---------------------------------------------------------------------------
__device__ __forceinline__ uint32_t smem_u32(const void* p) {
    uint32_t a;
    asm("{ .reg .u64 t; cvta.to.shared.u64 t, %1; cvt.u32.u64 %0, t; }" : "=r"(a) : "l"(p));
    return a;
}
__device__ __forceinline__ uint32_t sw64(uint32_t b) { return b ^ ((b >> 3) & 0x30); }

__device__ __forceinline__ void cp16(uint32_t smem, const void* gmem, int srcBytes) {
    asm volatile("cp.async.cg.shared.global [%0], [%1], 16, %2;"
                 :: "r"(smem), "l"(gmem), "r"(srcBytes));
}
__device__ __forceinline__ void cp_commit() {
    asm volatile("cp.async.commit_group;" ::: "memory");
}
template<int N>
__device__ __forceinline__ void cp_wait() {
    asm volatile("cp.async.wait_group %0;" :: "n"(N) : "memory");
}

__device__ __forceinline__ void ldsm_x4(uint32_t* r, uint32_t addr) {
    asm volatile("ldmatrix.sync.aligned.m8n8.x4.shared.b16 {%0,%1,%2,%3}, [%4];"
                 : "=r"(r[0]), "=r"(r[1]), "=r"(r[2]), "=r"(r[3]) : "r"(addr));
}
__device__ __forceinline__ void ldsm_x2(uint32_t* r, uint32_t addr) {
    asm volatile("ldmatrix.sync.aligned.m8n8.x2.shared.b16 {%0,%1}, [%2];"
                 : "=r"(r[0]), "=r"(r[1]) : "r"(addr));
}
__device__ __forceinline__ void mma16816(float* c, const uint32_t* a, const uint32_t* b) {
    asm volatile("mma.sync.aligned.m16n8k16.row.col.f32.bf16.bf16.f32 "
                 "{%0,%1,%2,%3}, {%4,%5,%6,%7}, {%8,%9}, {%0,%1,%2,%3};"
                 : "+f"(c[0]), "+f"(c[1]), "+f"(c[2]), "+f"(c[3])
                 : "r"(a[0]), "r"(a[1]), "r"(a[2]), "r"(a[3]), "r"(b[0]), "r"(b[1]));
}

__device__ __forceinline__ void split_f32(float v, __nv_bfloat16& h, __nv_bfloat16& l) {
    h = __float2bfloat16(v);
    l = __float2bfloat16(v - __bfloat162float(h));
}
// pack 4 f32 -> 2x bf16x2 (hi) + 2x bf16x2 (lo), as uint2 each
__device__ __forceinline__ void split4(float4 v, uint2& hi, uint2& lo) {
    __nv_bfloat16 h0, l0, h1, l1, h2, l2, h3, l3;
    split_f32(v.x, h0, l0); split_f32(v.y, h1, l1);
    split_f32(v.z, h2, l2); split_f32(v.w, h3, l3);
    __nv_bfloat162 a = __halves2bfloat162(h0, h1), b = __halves2bfloat162(h2, h3);
    __nv_bfloat162 c = __halves2bfloat162(l0, l1), d = __halves2bfloat162(l2, l3);
    hi = make_uint2(*(uint32_t*)&a, *(uint32_t*)&b);
    lo = make_uint2(*(uint32_t*)&c, *(uint32_t*)&d);
}

__global__ void split_kernel(const float* __restrict__ src,
                             __nv_bfloat16* __restrict__ hi,
                             __nv_bfloat16* __restrict__ lo, int n4)
{
    int i = blockIdx.x * blockDim.x + threadIdx.x;
    if (i < n4) {
        float4 v = ((const float4*)src)[i];
        uint2 h, l; split4(v, h, l);
        ((uint2*)hi)[i] = h;
        ((uint2*)lo)[i] = l;
    }
}

// ---------------------------------------------------------------------------
// RMSNorm -> hi/lo bf16
// ---------------------------------------------------------------------------
__global__ void rmsnorm_kernel(const float* __restrict__ x,
                               const float* __restrict__ w,
                               __nv_bfloat16* __restrict__ oh,
                               __nv_bfloat16* __restrict__ ol)
{
    int row = blockIdx.x;
    const float* xr = x + (size_t)row * D_;
    float s = 0.f;
    for (int i = threadIdx.x; i < D_ / 4; i += 256) {
        float4 v = ((const float4*)xr)[i];
        s += v.x * v.x + v.y * v.y + v.z * v.z + v.w * v.w;
    }
    __shared__ float red[8];
    for (int off = 16; off; off >>= 1) s += __shfl_xor_sync(0xffffffffu, s, off);
    if ((threadIdx.x & 31) == 0) red[threadIdx.x >> 5] = s;
    __syncthreads();
    if (threadIdx.x < 8) {
        float t = red[threadIdx.x];
        t += __shfl_xor_sync(0xffu, t, 4);
        t += __shfl_xor_sync(0xffu, t, 2);
        t += __shfl_xor_sync(0xffu, t, 1);
        if (threadIdx.x == 0) red[0] = t;
    }
    __syncthreads();
    float scale = rsqrtf(red[0] * (1.f / D_) + 1.1920929e-7f);
    for (int i = threadIdx.x; i < D_ / 4; i += 256) {
        float4 v = ((const float4*)xr)[i];
        float4 wv = ((const float4*)w)[i];
        v.x *= scale * wv.x; v.y *= scale * wv.y;
        v.z *= scale * wv.z; v.w *= scale * wv.w;
        uint2 h, l; split4(v, h, l);
        ((uint2*)(oh + (size_t)row * D_))[i] = h;
        ((uint2*)(ol + (size_t)row * D_))[i] = l;
    }
}

// ---------------------------------------------------------------------------
// Tensor-core GEMM via mma.sync (bf16 hi/lo emulated fp32)
// ---------------------------------------------------------------------------
#define GSTAGE 32768

template<int EPI>
__global__ void __launch_bounds__(256)
gemm_tc_kernel(const __nv_bfloat16* __restrict__ Ah, const __nv_bfloat16* __restrict__ Al, int lda,
               const __nv_bfloat16* __restrict__ Bh, const __nv_bfloat16* __restrict__ Bl, int ldb,
               const float* __restrict__ aux, float* __restrict__ C,
               int N, int ldc, int kLen)
{
    extern __shared__ char smem[];
    uint32_t sb = smem_u32(smem);
    int tid = threadIdx.x, wid = tid >> 5, lid = tid & 31;
    int m0 = blockIdx.y * 128, n0 = blockIdx.x * 128;
    int kStart = blockIdx.z * kLen;
    int bRows = N - n0; if (bRows > 128) bRows = 128;
    int wm = (wid >> 2) * 64, wn = (wid & 3) * 32;

    float acc[4][4][4];
#pragma unroll
    for (int i = 0; i < 4; i++)
#pragma unroll
        for (int j = 0; j < 4; j++)
#pragma unroll
            for (int k = 0; k < 4; k++) acc[i][j][k] = 0.f;

    int nCh = kLen / 32;

    auto load_chunk = [&](int s, int k0) {
        uint32_t st = sb + s * GSTAGE;
#pragma unroll
        for (int p = 0; p < 2; p++) {
            int idx = tid + p * 256;
            int r = idx >> 2, c = idx & 3;
            uint32_t so = sw64((uint32_t)(r * 64 + c * 16));
            cp16(st + so, Ah + (size_t)(m0 + r) * lda + k0 + c * 8, 16);
            cp16(st + 8192 + so, Al + (size_t)(m0 + r) * lda + k0 + c * 8, 16);
            int rb = (r < bRows) ? r : (bRows - 1);
            int ok = (r < bRows) ? 16 : 0;
            cp16(st + 16384 + so, Bh + (size_t)(n0 + rb) * ldb + k0 + c * 8, ok);
            cp16(st + 24576 + so, Bl + (size_t)(n0 + rb) * ldb + k0 + c * 8, ok);
        }
        cp_commit();
    };

    load_chunk(0, kStart);

    for (int ch = 0; ch < nCh; ch++) {
        bool hasNext = (ch + 1 < nCh);
        if (hasNext) load_chunk((ch + 1) & 1, kStart + (ch + 1) * 32);
        if (hasNext) cp_wait<1>(); else cp_wait<0>();
        __syncthreads();

        uint32_t st = sb + (ch & 1) * GSTAGE;
#pragma unroll
        for (int ks = 0; ks < 2; ks++) {
            uint32_t ah[4][4], al[4][4], bh[4][2], bl[4][2];
#pragma unroll
            for (int mt = 0; mt < 4; mt++) {
                int row = wm + mt * 16 + (lid & 15);
                int kk = ks * 16 + (lid >> 4) * 8;
                uint32_t so = sw64((uint32_t)(row * 64 + kk * 2));
                ldsm_x4(ah[mt], st + so);
                ldsm_x4(al[mt], st + 8192 + so);
            }
#pragma unroll
            for (int nt = 0; nt < 4; nt++) {
                int row = wn + nt * 8 + (lid & 7);
                int kk = ks * 16 + ((lid >> 3) & 1) * 8;
                uint32_t so = sw64((uint32_t)(row * 64 + kk * 2));
                ldsm_x2(bh[nt], st + 16384 + so);
                ldsm_x2(bl[nt], st + 24576 + so);
            }
#pragma unroll
            for (int mt = 0; mt < 4; mt++)
#pragma unroll
                for (int nt = 0; nt < 4; nt++) {
                    mma16816(acc[mt][nt], ah[mt], bh[nt]);
                    mma16816(acc[mt][nt], ah[mt], bl[nt]);
                    mma16816(acc[mt][nt], al[mt], bh[nt]);
                }
        }
        __syncthreads();
    }

    int gid = lid >> 2, tig = lid & 3;
#pragma unroll
    for (int mt = 0; mt < 4; mt++) {
        int r0 = m0 + wm + mt * 16 + gid;
#pragma unroll
        for (int nt = 0; nt < 4; nt++) {
            int cc = n0 + wn + nt * 8 + tig * 2;
            float* a = acc[mt][nt];
#pragma unroll
            for (int half = 0; half < 2; half++) {
                int r = r0 + half * 8;
                float v0 = a[half * 2 + 0], v1 = a[half * 2 + 1];
                size_t o = (size_t)r * ldc + cc;
                if (EPI == 0) {
                    *(float2*)&C[o] = make_float2(v0, v1);
                } else if (EPI == 1) {
                    if (cc < N) { atomicAdd(&C[o], v0); atomicAdd(&C[o + 1], v1); }
                } else if (EPI == 2) {
                    float2 rr = *(const float2*)&aux[o];
                    *(float2*)&C[o] = make_float2(v0 + rr.x, v1 + rr.y);
                } else {
                    float b0 = aux[cc], b1 = aux[cc + 1];
                    float s0 = v0 + b0, s1 = v1 + b1;
                    s0 = (s0 > 20.f) ? s0 : log1pf(__expf(s0));
                    s1 = (s1 > 20.f) ? s1 : log1pf(__expf(s1));
                    *(float2*)&C[o] = make_float2(s0, s1);
                }
            }
        }
    }
}

// ---------------------------------------------------------------------------
// Depthwise causal conv (width 4) + bias + SiLU, float4-vectorized.
// ---------------------------------------------------------------------------
__global__ void conv_silu_kernel(const float* __restrict__ xz,
                                 const float* __restrict__ cw,
                                 const float* __restrict__ cb,
                                 float* __restrict__ u,
                                 __nv_bfloat16* __restrict__ uh,
                                 __nv_bfloat16* __restrict__ ul)
{
    int idx = blockIdx.x * blockDim.x + threadIdx.x;   // over MROWS * DI_/4
    if (idx >= MROWS * (DI_ / 4)) return;
    int i4 = idx % (DI_ / 4);
    int bt = idx / (DI_ / 4);
    int t  = bt % T_;
    int i  = i4 * 4;

    float4 w0 = ((const float4*)cw)[i + 0];   // weights for channel i   (4 taps)
    float4 w1 = ((const float4*)cw)[i + 1];
    float4 w2 = ((const float4*)cw)[i + 2];
    float4 w3 = ((const float4*)cw)[i + 3];
    float4 bb = ((const float4*)cb)[i4];

    float4 x3 = (t >= 3) ? *(const float4*)&xz[(size_t)(bt - 3) * (2 * DI_) + i] : make_float4(0, 0, 0, 0);
    float4 x2 = (t >= 2) ? *(const float4*)&xz[(size_t)(bt - 2) * (2 * DI_) + i] : make_float4(0, 0, 0, 0);
    float4 x1 = (t >= 1) ? *(const float4*)&xz[(size_t)(bt - 1) * (2 * DI_) + i] : make_float4(0, 0, 0, 0);
    float4 x0 = *(const float4*)&xz[(size_t)bt * (2 * DI_) + i];

    float4 r;
    r.x = bb.x + w0.x * x3.x + w0.y * x2.x + w0.z * x1.x + w0.w * x0.x;
    r.y = bb.y + w1.x * x3.y + w1.y * x2.y + w1.z * x1.y + w1.w * x0.y;
    r.z = bb.z + w2.x * x3.z + w2.y * x2.z + w2.z * x1.z + w2.w * x0.z;
    r.w = bb.w + w3.x * x3.w + w3.y * x2.w + w3.z * x1.w + w3.w * x0.w;

    r.x = r.x / (1.f + __expf(-r.x));
    r.y = r.y / (1.f + __expf(-r.y));
    r.z = r.z / (1.f + __expf(-r.z));
    r.w = r.w / (1.f + __expf(-r.w));

    ((float4*)u)[idx] = r;
    uint2 h, l; split4(r, h, l);
    ((uint2*)uh)[idx] = h;
    ((uint2*)ul)[idx] = l;
}

// ---------------------------------------------------------------------------
// Selective scan v2: smem chunk staging with cp.async double buffering.
// Block = 16 channels x 16 states (256 thr). 16 chunks of 64 timesteps.
// ---------------------------------------------------------------------------
#define SCH 64
#define NCHK (T_ / SCH)

__global__ void __launch_bounds__(256)
scan_kernel(const float* __restrict__ delta,
            const float* __restrict__ u,
            const float* __restrict__ xdbc,
            const float* __restrict__ xz,
            const float* __restrict__ A_log,
            const float* __restrict__ Dp,
            __nv_bfloat16* __restrict__ yh,
            __nv_bfloat16* __restrict__ yl)
{
    int b  = blockIdx.x >> 7;          // 128 channel-groups per batch
    int ib = blockIdx.x & 127;
    int i0 = ib * 16;
    int tid = threadIdx.x;
    int ci = tid >> 4;                  // channel within group
    int s  = tid & 15;                  // state
    int i  = i0 + ci;

    __shared__ float sd[2][SCH][16];
    __shared__ float su[2][SCH][16];
    __shared__ float sB[2][SCH][16];
    __shared__ float sC[2][SCH][16];
    __shared__ float sz[2][SCH][16];
    __shared__ float sy[SCH][16];

    float a  = -__expf(A_log[i * DS_ + s]);
    float dp = Dp[i];
    float h  = 0.f;

    int lr = tid >> 2, lc = (tid & 3) * 4;     // loader: row 0..63, float-offset 0/4/8/12

    auto load_chunk = [&](int stg, int t0) {
        size_t bt = (size_t)(b * T_ + t0 + lr);
        cp16(smem_u32(&sd[stg][lr][lc]), delta + bt * DI_ + i0 + lc, 16);
        cp16(smem_u32(&su[stg][lr][lc]), u + bt * DI_ + i0 + lc, 16);
        cp16(smem_u32(&sB[stg][lr][lc]), xdbc + bt * XDBC_ + R_ + lc, 16);
        cp16(smem_u32(&sC[stg][lr][lc]), xdbc + bt * XDBC_ + R_ + DS_ + lc, 16);
        cp16(smem_u32(&sz[stg][lr][lc]), xz + bt * (2 * DI_) + DI_ + i0 + lc, 16);
        cp_commit();
    };

    load_chunk(0, 0);

    for (int c = 0; c < NCHK; c++) {
        bool hasNext = (c + 1 < NCHK);
        if (hasNext) load_chunk((c + 1) & 1, (c + 1) * SCH);
        if (hasNext) cp_wait<1>(); else cp_wait<0>();
        __syncthreads();

        int stg = c & 1;
#pragma unroll 4
        for (int t = 0; t < SCH; t++) {
            float d  = sd[stg][t][ci];
            float uu = su[stg][t][ci];
            float Bv = sB[stg][t][s];
            float Cv = sC[stg][t][s];
            h = __expf(d * a) * h + (d * uu) * Bv;
            float p = h * Cv;
            p += __shfl_xor_sync(0xffffffffu, p, 8, 16);
            p += __shfl_xor_sync(0xffffffffu, p, 4, 16);
            p += __shfl_xor_sync(0xffffffffu, p, 2, 16);
            p += __shfl_xor_sync(0xffffffffu, p, 1, 16);
            if (s == 0) {
                float z = sz[stg][t][ci];
                sy[t][ci] = (p + uu * dp) * (z / (1.f + __expf(-z)));
            }
        }
        __syncthreads();

        // store y chunk (hi/lo bf16), coalesced
        {
            size_t bt = (size_t)(b * T_ + c * SCH + lr);
            float4 v = *(float4*)&sy[lr][lc];
            uint2 hh, ll; split4(v, hh, ll);
            *(uint2*)(yh + bt * DI_ + i0 + lc) = hh;
            *(uint2*)(yl + bt * DI_ + i0 + lc) = ll;
        }
        __syncthreads();
    }
}

// ---------------------------------------------------------------------------
// Launch
// ---------------------------------------------------------------------------
extern "C" void kernel_launch(void* const* d_in, const int* in_sizes, int n_in,
                              void* d_out, int out_size)
{
    const float* x          = (const float*)d_in[0];
    const float* norm_w     = (const float*)d_in[1];
    const float* in_proj_w  = (const float*)d_in[2];
    const float* conv_w     = (const float*)d_in[3];
    const float* conv_b     = (const float*)d_in[4];
    const float* x_proj_w   = (const float*)d_in[5];
    const float* dt_proj_w  = (const float*)d_in[6];
    const float* dt_proj_b  = (const float*)d_in[7];
    const float* A_log      = (const float*)d_in[8];
    const float* D_param    = (const float*)d_in[9];
    const float* out_proj_w = (const float*)d_in[10];
    float* out = (float*)d_out;

    float *xz, *u, *xdbc, *delta;
    __nv_bfloat16 *xnh, *xnl, *uh, *ul, *yh, *yl, *xdh, *xdl;
    __nv_bfloat16 *winh, *winl, *wouth, *woutl, *wxph, *wxpl, *wdth, *wdtl;
    cudaGetSymbolAddress((void**)&xz,    g_xz);
    cudaGetSymbolAddress((void**)&u,     g_u);
    cudaGetSymbolAddress((void**)&xdbc,  g_xdbc);
    cudaGetSymbolAddress((void**)&delta, g_delta);
    cudaGetSymbolAddress((void**)&xnh,   g_xn_h);
    cudaGetSymbolAddress((void**)&xnl,   g_xn_l);
    cudaGetSymbolAddress((void**)&uh,    g_u_h);
    cudaGetSymbolAddress((void**)&ul,    g_u_l);
    cudaGetSymbolAddress((void**)&yh,    g_y_h);
    cudaGetSymbolAddress((void**)&yl,    g_y_l);
    cudaGetSymbolAddress((void**)&xdh,   g_xdbc_h);
    cudaGetSymbolAddress((void**)&xdl,   g_xdbc_l);
    cudaGetSymbolAddress((void**)&winh,  g_win_h);
    cudaGetSymbolAddress((void**)&winl,  g_win_l);
    cudaGetSymbolAddress((void**)&wouth, g_wout_h);
    cudaGetSymbolAddress((void**)&woutl, g_wout_l);
    cudaGetSymbolAddress((void**)&wxph,  g_wxp_h);
    cudaGetSymbolAddress((void**)&wxpl,  g_wxp_l);
    cudaGetSymbolAddress((void**)&wdth,  g_wdt_h);
    cudaGetSymbolAddress((void**)&wdtl,  g_wdt_l);

    int smem = 2 * GSTAGE;
    cudaFuncSetAttribute(gemm_tc_kernel<0>, cudaFuncAttributeMaxDynamicSharedMemorySize, smem);
    cudaFuncSetAttribute(gemm_tc_kernel<1>, cudaFuncAttributeMaxDynamicSharedMemorySize, smem);
    cudaFuncSetAttribute(gemm_tc_kernel<2>, cudaFuncAttributeMaxDynamicSharedMemorySize, smem);
    cudaFuncSetAttribute(gemm_tc_kernel<3>, cudaFuncAttributeMaxDynamicSharedMemorySize, smem);

    // 0. Split weights into bf16 hi/lo (float4 vectorized)
    split_kernel<<<(2 * DI_ * D_ / 4 + 255) / 256, 256>>>(in_proj_w, winh, winl, 2 * DI_ * D_ / 4);
    split_kernel<<<(D_ * DI_ / 4 + 255) / 256, 256>>>(out_proj_w, wouth, woutl, D_ * DI_ / 4);
    split_kernel<<<(XDBC_ * DI_ / 4 + 255) / 256, 256>>>(x_proj_w, wxph, wxpl, XDBC_ * DI_ / 4);
    split_kernel<<<(DI_ * R_ / 4 + 255) / 256, 256>>>(dt_proj_w, wdth, wdtl, DI_ * R_ / 4);

    // 1. RMSNorm -> xn hi/lo
    rmsnorm_kernel<<<MROWS, 256>>>(x, norm_w, xnh, xnl);

    // 2. in_proj
    gemm_tc_kernel<0><<<dim3(2 * DI_ / 128, MROWS / 128, 1), 256, smem>>>(
        xnh, xnl, D_, winh, winl, D_, nullptr, xz, 2 * DI_, 2 * DI_, D_);

    // 3. conv + silu -> u (f32 + hi/lo)
    conv_silu_kernel<<<(MROWS * DI_ / 4 + 255) / 256, 256>>>(xz, conv_w, conv_b, u, uh, ul);

    // 4. x_proj (split-K=8, atomics)
    cudaMemsetAsync(xdbc, 0, (size_t)MROWS * XDBC_ * sizeof(float));
    gemm_tc_kernel<1><<<dim3(1, MROWS / 128, 8), 256, smem>>>(
        uh, ul, DI_, wxph, wxpl, DI_, nullptr, xdbc, XDBC_, XDBC_, DI_ / 8);

    // 4b. split xdbc -> bf16 hi/lo
    split_kernel<<<(MROWS * XDBC_ / 4 + 255) / 256, 256>>>(xdbc, xdh, xdl, MROWS * XDBC_ / 4);

    // 5. dt_proj + softplus
    gemm_tc_kernel<3><<<dim3(DI_ / 128, MROWS / 128, 1), 256, smem>>>(
        xdh, xdl, XDBC_, wdth, wdtl, R_, dt_proj_b, delta, DI_, DI_, R_);

    // 6. selective scan (smem-staged, fused gate + skip)
    scan_kernel<<<B_ * (DI_ / 16), 256>>>(delta, u, xdbc, xz, A_log, D_param, yh, yl);

    // 7. out_proj + residual
    gemm_tc_kernel<2><<<dim3(D_ / 128, MROWS / 128, 1), 256, smem>>>(
        yh, yl, DI_, wouth, woutl, DI_, x, out, D_, D_, DI_);
}

// round 6
// speedup vs baseline: 3.1635x; 1.0492x over previous
#include <cuda_runtime.h>
#include <cuda_bf16.h>
#include <math.h>
#include <stdint.h>

// Problem dims
#define B_   2
#define T_   1024
#define D_   1024
#define DI_  2048          // D_INNER
#define DS_  16            // D_STATE
#define R_   64            // DT_RANK
#define XDBC_ 96           // R_ + 2*DS_
#define MROWS (B_*T_)      // 2048

// ---------------------------------------------------------------------------
// Scratch (device globals; no allocation allowed)
// ---------------------------------------------------------------------------
__device__ __align__(256) float g_xz[MROWS * 2 * DI_];
__device__ __align__(256) float g_u[MROWS * DI_];
__device__ __align__(256) float g_xdbc[MROWS * XDBC_];
__device__ __align__(256) float g_delta[MROWS * DI_];

__device__ __align__(256) __nv_bfloat16 g_xn_h[MROWS * D_];
__device__ __align__(256) __nv_bfloat16 g_xn_l[MROWS * D_];
__device__ __align__(256) __nv_bfloat16 g_u_h[MROWS * DI_];
__device__ __align__(256) __nv_bfloat16 g_u_l[MROWS * DI_];
__device__ __align__(256) __nv_bfloat16 g_y_h[MROWS * DI_];
__device__ __align__(256) __nv_bfloat16 g_y_l[MROWS * DI_];
__device__ __align__(256) __nv_bfloat16 g_xdbc_h[MROWS * XDBC_];
__device__ __align__(256) __nv_bfloat16 g_xdbc_l[MROWS * XDBC_];
__device__ __align__(256) __nv_bfloat16 g_win_h[2 * DI_ * D_];
__device__ __align__(256) __nv_bfloat16 g_win_l[2 * DI_ * D_];
__device__ __align__(256) __nv_bfloat16 g_wout_h[D_ * DI_];
__device__ __align__(256) __nv_bfloat16 g_wout_l[D_ * DI_];
__device__ __align__(256) __nv_bfloat16 g_wxp_h[XDBC_ * DI_];
__device__ __align__(256) __nv_bfloat16 g_wxp_l[XDBC_ * DI_];
__device__ __align__(256) __nv_bfloat16 g_wdt_h[DI_ * R_];
__device__ __align__(256) __nv_bfloat16 g_wdt_l[DI_ * R_];

// ---------------------------------------------------------------------------
// Helpers
// ---------------------------------------------------------------------------
__device__ __forceinline__ uint32_t smem_u32(const void* p) {
    uint32_t a;
    asm("{ .reg .u64 t; cvta.to.shared.u64 t, %1; cvt.u32.u64 %0, t; }" : "=r"(a) : "l"(p));
    return a;
}
__device__ __forceinline__ uint32_t sw64(uint32_t b) { return b ^ ((b >> 3) & 0x30); }

__device__ __forceinline__ void cp16(uint32_t smem, const void* gmem, int srcBytes) {
    asm volatile("cp.async.cg.shared.global [%0], [%1], 16, %2;"
                 :: "r"(smem), "l"(gmem), "r"(srcBytes));
}
__device__ __forceinline__ void cp_commit() {
    asm volatile("cp.async.commit_group;" ::: "memory");
}
template<int N>
__device__ __forceinline__ void cp_wait() {
    asm volatile("cp.async.wait_group %0;" :: "n"(N) : "memory");
}

__device__ __forceinline__ void ldsm_x4(uint32_t* r, uint32_t addr) {
    asm volatile("ldmatrix.sync.aligned.m8n8.x4.shared.b16 {%0,%1,%2,%3}, [%4];"
                 : "=r"(r[0]), "=r"(r[1]), "=r"(r[2]), "=r"(r[3]) : "r"(addr));
}
__device__ __forceinline__ void ldsm_x2(uint32_t* r, uint32_t addr) {
    asm volatile("ldmatrix.sync.aligned.m8n8.x2.shared.b16 {%0,%1}, [%2];"
                 : "=r"(r[0]), "=r"(r[1]) : "r"(addr));
}
__device__ __forceinline__ void mma16816(float* c, const uint32_t* a, const uint32_t* b) {
    asm volatile("mma.sync.aligned.m16n8k16.row.col.f32.bf16.bf16.f32 "
                 "{%0,%1,%2,%3}, {%4,%5,%6,%7}, {%8,%9}, {%0,%1,%2,%3};"
                 : "+f"(c[0]), "+f"(c[1]), "+f"(c[2]), "+f"(c[3])
                 : "r"(a[0]), "r"(a[1]), "r"(a[2]), "r"(a[3]), "r"(b[0]), "r"(b[1]));
}

__device__ __forceinline__ void split_f32(float v, __nv_bfloat16& h, __nv_bfloat16& l) {
    h = __float2bfloat16(v);
    l = __float2bfloat16(v - __bfloat162float(h));
}
__device__ __forceinline__ void split4(float4 v, uint2& hi, uint2& lo) {
    __nv_bfloat16 h0, l0, h1, l1, h2, l2, h3, l3;
    split_f32(v.x, h0, l0); split_f32(v.y, h1, l1);
    split_f32(v.z, h2, l2); split_f32(v.w, h3, l3);
    __nv_bfloat162 a = __halves2bfloat162(h0, h1), b = __halves2bfloat162(h2, h3);
    __nv_bfloat162 c = __halves2bfloat162(l0, l1), d = __halves2bfloat162(l2, l3);
    hi = make_uint2(*(uint32_t*)&a, *(uint32_t*)&b);
    lo = make_uint2(*(uint32_t*)&c, *(uint32_t*)&d);
}

// Segment sizes (in float4 units) for the fused weight split
#define S0_ (2 * DI_ * D_ / 4)
#define S1_ (D_ * DI_ / 4)
#define S2_ (XDBC_ * DI_ / 4)
#define S3_ (DI_ * R_ / 4)

__global__ void split_weights_kernel(
    const float* __restrict__ w0, __nv_bfloat16* __restrict__ h0, __nv_bfloat16* __restrict__ l0,
    const float* __restrict__ w1, __nv_bfloat16* __restrict__ h1, __nv_bfloat16* __restrict__ l1,
    const float* __restrict__ w2, __nv_bfloat16* __restrict__ h2, __nv_bfloat16* __restrict__ l2,
    const float* __restrict__ w3, __nv_bfloat16* __restrict__ h3, __nv_bfloat16* __restrict__ l3)
{
    int i = blockIdx.x * blockDim.x + threadIdx.x;
    const float* src; __nv_bfloat16* dh; __nv_bfloat16* dl; int off;
    if (i < S0_)                       { src = w0; dh = h0; dl = l0; off = i; }
    else if (i < S0_ + S1_)            { src = w1; dh = h1; dl = l1; off = i - S0_; }
    else if (i < S0_ + S1_ + S2_)      { src = w2; dh = h2; dl = l2; off = i - S0_ - S1_; }
    else if (i < S0_ + S1_ + S2_ + S3_){ src = w3; dh = h3; dl = l3; off = i - S0_ - S1_ - S2_; }
    else return;
    float4 v = ((const float4*)src)[off];
    uint2 h, l; split4(v, h, l);
    ((uint2*)dh)[off] = h;
    ((uint2*)dl)[off] = l;
}

__global__ void split_kernel(const float* __restrict__ src,
                             __nv_bfloat16* __restrict__ hi,
                             __nv_bfloat16* __restrict__ lo, int n4)
{
    int i = blockIdx.x * blockDim.x + threadIdx.x;
    if (i < n4) {
        float4 v = ((const float4*)src)[i];
        uint2 h, l; split4(v, h, l);
        ((uint2*)hi)[i] = h;
        ((uint2*)lo)[i] = l;
    }
}

__global__ void copy_kernel(const float* __restrict__ src, float* __restrict__ dst, int n4)
{
    int i = blockIdx.x * blockDim.x + threadIdx.x;
    if (i < n4) ((float4*)dst)[i] = ((const float4*)src)[i];
}

// ---------------------------------------------------------------------------
// RMSNorm -> hi/lo bf16
// ---------------------------------------------------------------------------
__global__ void rmsnorm_kernel(const float* __restrict__ x,
                               const float* __restrict__ w,
                               __nv_bfloat16* __restrict__ oh,
                               __nv_bfloat16* __restrict__ ol)
{
    int row = blockIdx.x;
    const float* xr = x + (size_t)row * D_;
    float s = 0.f;
    for (int i = threadIdx.x; i < D_ / 4; i += 256) {
        float4 v = ((const float4*)xr)[i];
        s += v.x * v.x + v.y * v.y + v.z * v.z + v.w * v.w;
    }
    __shared__ float red[8];
    for (int off = 16; off; off >>= 1) s += __shfl_xor_sync(0xffffffffu, s, off);
    if ((threadIdx.x & 31) == 0) red[threadIdx.x >> 5] = s;
    __syncthreads();
    if (threadIdx.x < 8) {
        float t = red[threadIdx.x];
        t += __shfl_xor_sync(0xffu, t, 4);
        t += __shfl_xor_sync(0xffu, t, 2);
        t += __shfl_xor_sync(0xffu, t, 1);
        if (threadIdx.x == 0) red[0] = t;
    }
    __syncthreads();
    float scale = rsqrtf(red[0] * (1.f / D_) + 1.1920929e-7f);
    for (int i = threadIdx.x; i < D_ / 4; i += 256) {
        float4 v = ((const float4*)xr)[i];
        float4 wv = ((const float4*)w)[i];
        v.x *= scale * wv.x; v.y *= scale * wv.y;
        v.z *= scale * wv.z; v.w *= scale * wv.w;
        uint2 h, l; split4(v, h, l);
        ((uint2*)(oh + (size_t)row * D_))[i] = h;
        ((uint2*)(ol + (size_t)row * D_))[i] = l;
    }
}

// ---------------------------------------------------------------------------
// Tensor-core GEMM via mma.sync (bf16 hi/lo emulated fp32).
// 256x128 CTA tile, BK=32, 512 threads (16 warps, 4x4), warp tile 64x32.
// 3-stage cp.async pipeline. Stage = Ah 16K | Al 16K | Bh 8K | Bl 8K = 48KB.
// EPI: 0 = store, 1 = atomicAdd (split-K), 3 = softplus(v + bias[n])
// ---------------------------------------------------------------------------
#define GSTG 49152
#define GSM  (3 * GSTG)

template<int EPI>
__global__ void __launch_bounds__(512)
gemm_tc_kernel(const __nv_bfloat16* __restrict__ Ah, const __nv_bfloat16* __restrict__ Al, int lda,
               const __nv_bfloat16* __restrict__ Bh, const __nv_bfloat16* __restrict__ Bl, int ldb,
               const float* __restrict__ aux, float* __restrict__ C,
               int N, int ldc, int kLen)
{
    extern __shared__ char smem[];
    uint32_t sb = smem_u32(smem);
    int tid = threadIdx.x, wid = tid >> 5, lid = tid & 31;
    int m0 = blockIdx.y * 256, n0 = blockIdx.x * 128;
    int kStart = blockIdx.z * kLen;
    int bRows = N - n0; if (bRows > 128) bRows = 128;
    int wm = (wid >> 2) * 64, wn = (wid & 3) * 32;

    float acc[4][4][4];
#pragma unroll
    for (int i = 0; i < 4; i++)
#pragma unroll
        for (int j = 0; j < 4; j++)
#pragma unroll
            for (int k = 0; k < 4; k++) acc[i][j][k] = 0.f;

    int nCh = kLen / 32;

    auto load_chunk = [&](int s, int k0) {
        uint32_t st = sb + s * GSTG;
        // A: 256 rows x 64B, hi+lo
#pragma unroll
        for (int p = 0; p < 2; p++) {
            int idx = tid + p * 512;
            int r = idx >> 2, c = idx & 3;
            uint32_t so = sw64((uint32_t)(r * 64 + c * 16));
            cp16(st + so, Ah + (size_t)(m0 + r) * lda + k0 + c * 8, 16);
            cp16(st + 16384 + so, Al + (size_t)(m0 + r) * lda + k0 + c * 8, 16);
        }
        // B: 128 rows x 64B, hi+lo
        {
            int r = tid >> 2, c = tid & 3;
            uint32_t so = sw64((uint32_t)(r * 64 + c * 16));
            int rb = (r < bRows) ? r : (bRows - 1);
            int ok = (r < bRows) ? 16 : 0;
            cp16(st + 32768 + so, Bh + (size_t)(n0 + rb) * ldb + k0 + c * 8, ok);
            cp16(st + 40960 + so, Bl + (size_t)(n0 + rb) * ldb + k0 + c * 8, ok);
        }
        cp_commit();
    };

    load_chunk(0, kStart);
    if (nCh > 1) load_chunk(1, kStart + 32);

    int stg = 0;
    for (int ch = 0; ch < nCh; ch++) {
        if (ch + 2 < nCh) {
            int s2 = stg + 2; if (s2 >= 3) s2 -= 3;
            load_chunk(s2, kStart + (ch + 2) * 32);
            cp_wait<2>();
        } else if (ch + 1 < nCh) {
            cp_wait<1>();
        } else {
            cp_wait<0>();
        }
        __syncthreads();

        uint32_t st = sb + stg * GSTG;
#pragma unroll
        for (int ks = 0; ks < 2; ks++) {
            uint32_t ah[4][4], al[4][4], bh[4][2], bl[4][2];
#pragma unroll
            for (int mt = 0; mt < 4; mt++) {
                int row = wm + mt * 16 + (lid & 15);
                int kk = ks * 16 + (lid >> 4) * 8;
                uint32_t so = sw64((uint32_t)(row * 64 + kk * 2));
                ldsm_x4(ah[mt], st + so);
                ldsm_x4(al[mt], st + 16384 + so);
            }
#pragma unroll
            for (int nt = 0; nt < 4; nt++) {
                int row = wn + nt * 8 + (lid & 7);
                int kk = ks * 16 + ((lid >> 3) & 1) * 8;
                uint32_t so = sw64((uint32_t)(row * 64 + kk * 2));
                ldsm_x2(bh[nt], st + 32768 + so);
                ldsm_x2(bl[nt], st + 40960 + so);
            }
#pragma unroll
            for (int mt = 0; mt < 4; mt++)
#pragma unroll
                for (int nt = 0; nt < 4; nt++) {
                    mma16816(acc[mt][nt], ah[mt], bh[nt]);
                    mma16816(acc[mt][nt], ah[mt], bl[nt]);
                    mma16816(acc[mt][nt], al[mt], bh[nt]);
                }
        }
        __syncthreads();
        if (++stg == 3) stg = 0;
    }

    int gid = lid >> 2, tig = lid & 3;
#pragma unroll
    for (int mt = 0; mt < 4; mt++) {
        int r0 = m0 + wm + mt * 16 + gid;
#pragma unroll
        for (int nt = 0; nt < 4; nt++) {
            int cc = n0 + wn + nt * 8 + tig * 2;
            float* a = acc[mt][nt];
#pragma unroll
            for (int half = 0; half < 2; half++) {
                int r = r0 + half * 8;
                float v0 = a[half * 2 + 0], v1 = a[half * 2 + 1];
                size_t o = (size_t)r * ldc + cc;
                if (EPI == 0) {
                    *(float2*)&C[o] = make_float2(v0, v1);
                } else if (EPI == 1) {
                    if (cc < N) { atomicAdd(&C[o], v0); atomicAdd(&C[o + 1], v1); }
                } else {
                    float b0 = aux[cc], b1 = aux[cc + 1];
                    float s0 = v0 + b0, s1 = v1 + b1;
                    s0 = (s0 > 20.f) ? s0 : log1pf(__expf(s0));
                    s1 = (s1 > 20.f) ? s1 : log1pf(__expf(s1));
                    *(float2*)&C[o] = make_float2(s0, s1);
                }
            }
        }
    }
}

// ---------------------------------------------------------------------------
// Depthwise causal conv (width 4) + bias + SiLU, float4-vectorized.
// ---------------------------------------------------------------------------
__global__ void conv_silu_kernel(const float* __restrict__ xz,
                                 const float* __restrict__ cw,
                                 const float* __restrict__ cb,
                                 float* __restrict__ u,
                                 __nv_bfloat16* __restrict__ uh,
                                 __nv_bfloat16* __restrict__ ul)
{
    int idx = blockIdx.x * blockDim.x + threadIdx.x;
    if (idx >= MROWS * (DI_ / 4)) return;
    int i4 = idx % (DI_ / 4);
    int bt = idx / (DI_ / 4);
    int t  = bt % T_;
    int i  = i4 * 4;

    float4 w0 = ((const float4*)cw)[i + 0];
    float4 w1 = ((const float4*)cw)[i + 1];
    float4 w2 = ((const float4*)cw)[i + 2];
    float4 w3 = ((const float4*)cw)[i + 3];
    float4 bb = ((const float4*)cb)[i4];

    float4 x3 = (t >= 3) ? *(const float4*)&xz[(size_t)(bt - 3) * (2 * DI_) + i] : make_float4(0, 0, 0, 0);
    float4 x2 = (t >= 2) ? *(const float4*)&xz[(size_t)(bt - 2) * (2 * DI_) + i] : make_float4(0, 0, 0, 0);
    float4 x1 = (t >= 1) ? *(const float4*)&xz[(size_t)(bt - 1) * (2 * DI_) + i] : make_float4(0, 0, 0, 0);
    float4 x0 = *(const float4*)&xz[(size_t)bt * (2 * DI_) + i];

    float4 r;
    r.x = bb.x + w0.x * x3.x + w0.y * x2.x + w0.z * x1.x + w0.w * x0.x;
    r.y = bb.y + w1.x * x3.y + w1.y * x2.y + w1.z * x1.y + w1.w * x0.y;
    r.z = bb.z + w2.x * x3.z + w2.y * x2.z + w2.z * x1.z + w2.w * x0.z;
    r.w = bb.w + w3.x * x3.w + w3.y * x2.w + w3.z * x1.w + w3.w * x0.w;

    r.x = r.x / (1.f + __expf(-r.x));
    r.y = r.y / (1.f + __expf(-r.y));
    r.z = r.z / (1.f + __expf(-r.z));
    r.w = r.w / (1.f + __expf(-r.w));

    ((float4*)u)[idx] = r;
    uint2 h, l; split4(r, h, l);
    ((uint2*)uh)[idx] = h;
    ((uint2*)ul)[idx] = l;
}

// ---------------------------------------------------------------------------
// Selective scan: smem chunk staging with cp.async double buffering.
// Block = 16 channels x 16 states (256 thr). Chunks of 64 timesteps.
// ---------------------------------------------------------------------------
#define SCH 64
#define NCHK (T_ / SCH)

__global__ void __launch_bounds__(256)
scan_kernel(const float* __restrict__ delta,
            const float* __restrict__ u,
            const float* __restrict__ xdbc,
            const float* __restrict__ xz,
            const float* __restrict__ A_log,
            const float* __restrict__ Dp,
            __nv_bfloat16* __restrict__ yh,
            __nv_bfloat16* __restrict__ yl)
{
    int b  = blockIdx.x >> 7;
    int ib = blockIdx.x & 127;
    int i0 = ib * 16;
    int tid = threadIdx.x;
    int ci = tid >> 4;
    int s  = tid & 15;
    int i  = i0 + ci;

    __shared__ float sd[2][SCH][16];
    __shared__ float su[2][SCH][16];
    __shared__ float sB[2][SCH][16];
    __shared__ float sC[2][SCH][16];
    __shared__ float sz[2][SCH][16];
    __shared__ float sy[SCH][16];

    float a  = -__expf(A_log[i * DS_ + s]);
    float dp = Dp[i];
    float h  = 0.f;

    int lr = tid >> 2, lc = (tid & 3) * 4;

    auto load_chunk = [&](int stg, int t0) {
        size_t bt = (size_t)(b * T_ + t0 + lr);
        cp16(smem_u32(&sd[stg][lr][lc]), delta + bt * DI_ + i0 + lc, 16);
        cp16(smem_u32(&su[stg][lr][lc]), u + bt * DI_ + i0 + lc, 16);
        cp16(smem_u32(&sB[stg][lr][lc]), xdbc + bt * XDBC_ + R_ + lc, 16);
        cp16(smem_u32(&sC[stg][lr][lc]), xdbc + bt * XDBC_ + R_ + DS_ + lc, 16);
        cp16(smem_u32(&sz[stg][lr][lc]), xz + bt * (2 * DI_) + DI_ + i0 + lc, 16);
        cp_commit();
    };

    load_chunk(0, 0);

    for (int c = 0; c < NCHK; c++) {
        bool hasNext = (c + 1 < NCHK);
        if (hasNext) load_chunk((c + 1) & 1, (c + 1) * SCH);
        if (hasNext) cp_wait<1>(); else cp_wait<0>();
        __syncthreads();

        int stg = c & 1;
#pragma unroll 4
        for (int t = 0; t < SCH; t++) {
            float d  = sd[stg][t][ci];
            float uu = su[stg][t][ci];
            float Bv = sB[stg][t][s];
            float Cv = sC[stg][t][s];
            h = __expf(d * a) * h + (d * uu) * Bv;
            float p = h * Cv;
            p += __shfl_xor_sync(0xffffffffu, p, 8, 16);
            p += __shfl_xor_sync(0xffffffffu, p, 4, 16);
            p += __shfl_xor_sync(0xffffffffu, p, 2, 16);
            p += __shfl_xor_sync(0xffffffffu, p, 1, 16);
            if (s == 0) {
                float z = sz[stg][t][ci];
                sy[t][ci] = (p + uu * dp) * (z / (1.f + __expf(-z)));
            }
        }
        __syncthreads();

        {
            size_t bt = (size_t)(b * T_ + c * SCH + lr);
            float4 v = *(float4*)&sy[lr][lc];
            uint2 hh, ll; split4(v, hh, ll);
            *(uint2*)(yh + bt * DI_ + i0 + lc) = hh;
            *(uint2*)(yl + bt * DI_ + i0 + lc) = ll;
        }
        __syncthreads();
    }
}

// ---------------------------------------------------------------------------
// Launch
// ---------------------------------------------------------------------------
extern "C" void kernel_launch(void* const* d_in, const int* in_sizes, int n_in,
                              void* d_out, int out_size)
{
    const float* x          = (const float*)d_in[0];
    const float* norm_w     = (const float*)d_in[1];
    const float* in_proj_w  = (const float*)d_in[2];
    const float* conv_w     = (const float*)d_in[3];
    const float* conv_b     = (const float*)d_in[4];
    const float* x_proj_w   = (const float*)d_in[5];
    const float* dt_proj_w  = (const float*)d_in[6];
    const float* dt_proj_b  = (const float*)d_in[7];
    const float* A_log      = (const float*)d_in[8];
    const float* D_param    = (const float*)d_in[9];
    const float* out_proj_w = (const float*)d_in[10];
    float* out = (float*)d_out;

    float *xz, *u, *xdbc, *delta;
    __nv_bfloat16 *xnh, *xnl, *uh, *ul, *yh, *yl, *xdh, *xdl;
    __nv_bfloat16 *winh, *winl, *wouth, *woutl, *wxph, *wxpl, *wdth, *wdtl;
    cudaGetSymbolAddress((void**)&xz,    g_xz);
    cudaGetSymbolAddress((void**)&u,     g_u);
    cudaGetSymbolAddress((void**)&xdbc,  g_xdbc);
    cudaGetSymbolAddress((void**)&delta, g_delta);
    cudaGetSymbolAddress((void**)&xnh,   g_xn_h);
    cudaGetSymbolAddress((void**)&xnl,   g_xn_l);
    cudaGetSymbolAddress((void**)&uh,    g_u_h);
    cudaGetSymbolAddress((void**)&ul,    g_u_l);
    cudaGetSymbolAddress((void**)&yh,    g_y_h);
    cudaGetSymbolAddress((void**)&yl,    g_y_l);
    cudaGetSymbolAddress((void**)&xdh,   g_xdbc_h);
    cudaGetSymbolAddress((void**)&xdl,   g_xdbc_l);
    cudaGetSymbolAddress((void**)&winh,  g_win_h);
    cudaGetSymbolAddress((void**)&winl,  g_win_l);
    cudaGetSymbolAddress((void**)&wouth, g_wout_h);
    cudaGetSymbolAddress((void**)&woutl, g_wout_l);
    cudaGetSymbolAddress((void**)&wxph,  g_wxp_h);
    cudaGetSymbolAddress((void**)&wxpl,  g_wxp_l);
    cudaGetSymbolAddress((void**)&wdth,  g_wdt_h);
    cudaGetSymbolAddress((void**)&wdtl,  g_wdt_l);

    cudaFuncSetAttribute(gemm_tc_kernel<0>, cudaFuncAttributeMaxDynamicSharedMemorySize, GSM);
    cudaFuncSetAttribute(gemm_tc_kernel<1>, cudaFuncAttributeMaxDynamicSharedMemorySize, GSM);
    cudaFuncSetAttribute(gemm_tc_kernel<3>, cudaFuncAttributeMaxDynamicSharedMemorySize, GSM);

    // 0. Split all weights into bf16 hi/lo (fused, float4-vectorized)
    {
        int total = S0_ + S1_ + S2_ + S3_;
        split_weights_kernel<<<(total + 255) / 256, 256>>>(
            in_proj_w, winh, winl, out_proj_w, wouth, woutl,
            x_proj_w, wxph, wxpl, dt_proj_w, wdth, wdtl);
    }

    // 1. RMSNorm -> xn hi/lo
    rmsnorm_kernel<<<MROWS, 256>>>(x, norm_w, xnh, xnl);

    // 2. in_proj: xz[2048,4096] = xn @ W^T   (256x128 tiles, 256 CTAs)
    gemm_tc_kernel<0><<<dim3(2 * DI_ / 128, MROWS / 256, 1), 512, GSM>>>(
        xnh, xnl, D_, winh, winl, D_, nullptr, xz, 2 * DI_, 2 * DI_, D_);

    // 3. conv + silu -> u (f32 + hi/lo)
    conv_silu_kernel<<<(MROWS * DI_ / 4 + 255) / 256, 256>>>(xz, conv_w, conv_b, u, uh, ul);

    // 4. x_proj: xdbc = u @ W^T (split-K=16, atomics)
    cudaMemsetAsync(xdbc, 0, (size_t)MROWS * XDBC_ * sizeof(float));
    gemm_tc_kernel<1><<<dim3(1, MROWS / 256, 16), 512, GSM>>>(
        uh, ul, DI_, wxph, wxpl, DI_, nullptr, xdbc, XDBC_, XDBC_, DI_ / 16);

    // 4b. split xdbc -> bf16 hi/lo
    split_kernel<<<(MROWS * XDBC_ / 4 + 255) / 256, 256>>>(xdbc, xdh, xdl, MROWS * XDBC_ / 4);

    // 5. dt_proj + softplus (128 CTAs)
    gemm_tc_kernel<3><<<dim3(DI_ / 128, MROWS / 256, 1), 512, GSM>>>(
        xdh, xdl, XDBC_, wdth, wdtl, R_, dt_proj_b, delta, DI_, DI_, R_);

    // 6. selective scan (fused gate + skip)
    scan_kernel<<<B_ * (DI_ / 16), 256>>>(delta, u, xdbc, xz, A_log, D_param, yh, yl);

    // 7. out_proj + residual: prefill out with residual, then split-K=2 atomicAdd
    copy_kernel<<<(MROWS * D_ / 4 + 255) / 256, 256>>>(x, out, MROWS * D_ / 4);
    gemm_tc_kernel<1><<<dim3(D_ / 128, MROWS / 256, 2), 512, GSM>>>(
        yh, yl, DI_, wouth, woutl, DI_, nullptr, out, D_, D_, DI_ / 2);
}

// round 8
// speedup vs baseline: 3.6758x; 1.1620x over previous
#include <cuda_runtime.h>
#include <cuda_bf16.h>
#include <math.h>
#include <stdint.h>

// Problem dims
#define B_   2
#define T_   1024
#define D_   1024
#define DI_  2048          // D_INNER
#define DS_  16            // D_STATE
#define R_   64            // DT_RANK
#define XDBC_ 96           // R_ + 2*DS_
#define MROWS (B_*T_)      // 2048

// ---------------------------------------------------------------------------
// Scratch (device globals; no allocation allowed)
// ---------------------------------------------------------------------------
__device__ __align__(256) float g_xz[MROWS * 2 * DI_];     // in_proj out (exact)
__device__ __align__(256) float g_u[MROWS * DI_];          // conv out (exact, scan input)
__device__ __align__(256) float g_ur[MROWS * DI_];         // conv out (tf32-rounded, GEMM input)
__device__ __align__(256) float g_xn[MROWS * D_];          // rmsnorm out (rounded)
__device__ __align__(256) float g_xdbc[MROWS * XDBC_];     // x_proj out (exact)
__device__ __align__(256) float g_delta[MROWS * DI_];      // dt_proj out (exact)
__device__ __align__(256) float g_y[MROWS * DI_];          // scan out (rounded)
__device__ __align__(256) float g_win[2 * DI_ * D_];       // rounded weights
__device__ __align__(256) float g_wout[D_ * DI_];
__device__ __align__(256) float g_wxp[XDBC_ * DI_];
__device__ __align__(256) float g_wdt[DI_ * R_];

// ---------------------------------------------------------------------------
// Helpers
// ---------------------------------------------------------------------------
__device__ __forceinline__ uint32_t smem_u32(const void* p) {
    uint32_t a;
    asm("{ .reg .u64 t; cvta.to.shared.u64 t, %1; cvt.u32.u64 %0, t; }" : "=r"(a) : "l"(p));
    return a;
}
// 128-byte-row swizzle: 16B-chunk bits [6:4] ^= row bits [9:7]
__device__ __forceinline__ uint32_t sw128(uint32_t b) { return b ^ ((b >> 3) & 0x70); }

__device__ __forceinline__ void cp16(uint32_t smem, const void* gmem, int srcBytes) {
    asm volatile("cp.async.cg.shared.global [%0], [%1], 16, %2;"
                 :: "r"(smem), "l"(gmem), "r"(srcBytes));
}
__device__ __forceinline__ void cp_commit() {
    asm volatile("cp.async.commit_group;" ::: "memory");
}
template<int N>
__device__ __forceinline__ void cp_wait() {
    asm volatile("cp.async.wait_group %0;" :: "n"(N) : "memory");
}

__device__ __forceinline__ void ldsm_x4(uint32_t* r, uint32_t addr) {
    asm volatile("ldmatrix.sync.aligned.m8n8.x4.shared.b16 {%0,%1,%2,%3}, [%4];"
                 : "=r"(r[0]), "=r"(r[1]), "=r"(r[2]), "=r"(r[3]) : "r"(addr));
}
__device__ __forceinline__ void ldsm_x2(uint32_t* r, uint32_t addr) {
    asm volatile("ldmatrix.sync.aligned.m8n8.x2.shared.b16 {%0,%1}, [%2];"
                 : "=r"(r[0]), "=r"(r[1]) : "r"(addr));
}
// m16n8k8 tf32 MMA: a[4], b[2], c[4] (f32 accum)
__device__ __forceinline__ void mma_tf32(float* c, const uint32_t* a, const uint32_t* b) {
    asm volatile("mma.sync.aligned.m16n8k8.row.col.f32.tf32.tf32.f32 "
                 "{%0,%1,%2,%3}, {%4,%5,%6,%7}, {%8,%9}, {%0,%1,%2,%3};"
                 : "+f"(c[0]), "+f"(c[1]), "+f"(c[2]), "+f"(c[3])
                 : "r"(a[0]), "r"(a[1]), "r"(a[2]), "r"(a[3]), "r"(b[0]), "r"(b[1]));
}

__device__ __forceinline__ float rtf32(float x) {
    float r;
    asm("cvt.rna.tf32.f32 %0, %1;" : "=f"(r) : "f"(x));
    return r;
}
__device__ __forceinline__ float4 rtf32_4(float4 v) {
    v.x = rtf32(v.x); v.y = rtf32(v.y); v.z = rtf32(v.z); v.w = rtf32(v.w);
    return v;
}

// ---------------------------------------------------------------------------
// Round all weights to tf32 (fused, float4-vectorized)
// ---------------------------------------------------------------------------
#define S0_ (2 * DI_ * D_ / 4)
#define S1_ (D_ * DI_ / 4)
#define S2_ (XDBC_ * DI_ / 4)
#define S3_ (DI_ * R_ / 4)

__global__ void round_weights_kernel(
    const float* __restrict__ w0, float* __restrict__ o0,
    const float* __restrict__ w1, float* __restrict__ o1,
    const float* __restrict__ w2, float* __restrict__ o2,
    const float* __restrict__ w3, float* __restrict__ o3)
{
    int i = blockIdx.x * blockDim.x + threadIdx.x;
    const float* src; float* dst; int off;
    if (i < S0_)                        { src = w0; dst = o0; off = i; }
    else if (i < S0_ + S1_)             { src = w1; dst = o1; off = i - S0_; }
    else if (i < S0_ + S1_ + S2_)       { src = w2; dst = o2; off = i - S0_ - S1_; }
    else if (i < S0_ + S1_ + S2_ + S3_) { src = w3; dst = o3; off = i - S0_ - S1_ - S2_; }
    else return;
    ((float4*)dst)[off] = rtf32_4(((const float4*)src)[off]);
}

__global__ void copy_kernel(const float* __restrict__ src, float* __restrict__ dst, int n4)
{
    int i = blockIdx.x * blockDim.x + threadIdx.x;
    if (i < n4) ((float4*)dst)[i] = ((const float4*)src)[i];
}

// ---------------------------------------------------------------------------
// RMSNorm -> tf32-rounded f32
// ---------------------------------------------------------------------------
__global__ void rmsnorm_kernel(const float* __restrict__ x,
                               const float* __restrict__ w,
                               float* __restrict__ o)
{
    int row = blockIdx.x;
    const float* xr = x + (size_t)row * D_;
    float s = 0.f;
    for (int i = threadIdx.x; i < D_ / 4; i += 256) {
        float4 v = ((const float4*)xr)[i];
        s += v.x * v.x + v.y * v.y + v.z * v.z + v.w * v.w;
    }
    __shared__ float red[8];
    for (int off = 16; off; off >>= 1) s += __shfl_xor_sync(0xffffffffu, s, off);
    if ((threadIdx.x & 31) == 0) red[threadIdx.x >> 5] = s;
    __syncthreads();
    if (threadIdx.x < 8) {
        float t = red[threadIdx.x];
        t += __shfl_xor_sync(0xffu, t, 4);
        t += __shfl_xor_sync(0xffu, t, 2);
        t += __shfl_xor_sync(0xffu, t, 1);
        if (threadIdx.x == 0) red[0] = t;
    }
    __syncthreads();
    float scale = rsqrtf(red[0] * (1.f / D_) + 1.1920929e-7f);
    for (int i = threadIdx.x; i < D_ / 4; i += 256) {
        float4 v = ((const float4*)xr)[i];
        float4 wv = ((const float4*)w)[i];
        v.x *= scale * wv.x; v.y *= scale * wv.y;
        v.z *= scale * wv.z; v.w *= scale * wv.w;
        ((float4*)(o + (size_t)row * D_))[i] = rtf32_4(v);
    }
}

// ---------------------------------------------------------------------------
// tf32 tensor-core GEMM:
//   C[M, N(ldc)] (op)= A[M,*](lda) @ W[N,*](ldb)^T over K slice [z*kLen, +kLen)
// 128x128 CTA tile, BK=32 (f32), 256 threads (8 warps 2x4), warp tile 64x32.
// 3-stage cp.async pipeline. Stage = A 16KB | B 16KB. Operands pre-rounded tf32.
// EPI: 0 = store, 1 = atomicAdd (split-K), 3 = softplus(v + bias[n])
// ---------------------------------------------------------------------------
#define GSTG 32768
#define GSM  (3 * GSTG)

template<int EPI>
__global__ void __launch_bounds__(256, 2)
gemm_tf32_kernel(const float* __restrict__ A, int lda,
                 const float* __restrict__ Bm, int ldb,
                 const float* __restrict__ aux, float* __restrict__ C,
                 int N, int ldc, int kLen)
{
    extern __shared__ char smem[];
    uint32_t sb = smem_u32(smem);
    int tid = threadIdx.x, wid = tid >> 5, lid = tid & 31;
    int m0 = blockIdx.y * 128, n0 = blockIdx.x * 128;
    int kStart = blockIdx.z * kLen;
    int bRows = N - n0; if (bRows > 128) bRows = 128;
    int wm = (wid >> 2) * 64, wn = (wid & 3) * 32;

    float acc[4][4][4];
#pragma unroll
    for (int i = 0; i < 4; i++)
#pragma unroll
        for (int j = 0; j < 4; j++)
#pragma unroll
            for (int k = 0; k < 4; k++) acc[i][j][k] = 0.f;

    int nCh = kLen / 32;

    auto load_chunk = [&](int s, int k0) {
        uint32_t st = sb + s * GSTG;
        // A: 128 rows x 128B (32 f32)
#pragma unroll
        for (int p = 0; p < 4; p++) {
            int idx = tid + p * 256;          // 0..1023
            int r = idx >> 3, c = idx & 7;    // row, 16B chunk
            uint32_t so = sw128((uint32_t)(r * 128 + c * 16));
            cp16(st + so, A + (size_t)(m0 + r) * lda + k0 + c * 4, 16);
        }
        // B: 128 rows x 128B
#pragma unroll
        for (int p = 0; p < 4; p++) {
            int idx = tid + p * 256;
            int r = idx >> 3, c = idx & 7;
            uint32_t so = sw128((uint32_t)(r * 128 + c * 16));
            int rb = (r < bRows) ? r : (bRows - 1);
            int ok = (r < bRows) ? 16 : 0;
            cp16(st + 16384 + so, Bm + (size_t)(n0 + rb) * ldb + k0 + c * 4, ok);
        }
        cp_commit();
    };

    load_chunk(0, kStart);
    if (nCh > 1) load_chunk(1, kStart + 32);

    int stg = 0;
    for (int ch = 0; ch < nCh; ch++) {
        if (ch + 2 < nCh) {
            int s2 = stg + 2; if (s2 >= 3) s2 -= 3;
            load_chunk(s2, kStart + (ch + 2) * 32);
            cp_wait<2>();
        } else if (ch + 1 < nCh) {
            cp_wait<1>();
        } else {
            cp_wait<0>();
        }
        __syncthreads();

        uint32_t stA = sb + stg * GSTG;
        uint32_t stB = stA + 16384;
#pragma unroll
        for (int ks = 0; ks < 4; ks++) {        // 4 x k8
            uint32_t af[4][4], bf[4][2];
#pragma unroll
            for (int mt = 0; mt < 4; mt++) {
                int row = wm + mt * 16 + (lid & 15);
                int chunk = ks * 2 + (lid >> 4);
                ldsm_x4(af[mt], stA + sw128((uint32_t)(row * 128 + chunk * 16)));
            }
#pragma unroll
            for (int nt = 0; nt < 4; nt++) {
                int row = wn + nt * 8 + (lid & 7);
                int chunk = ks * 2 + ((lid >> 3) & 1);
                ldsm_x2(bf[nt], stB + sw128((uint32_t)(row * 128 + chunk * 16)));
            }
#pragma unroll
            for (int mt = 0; mt < 4; mt++)
#pragma unroll
                for (int nt = 0; nt < 4; nt++)
                    mma_tf32(acc[mt][nt], af[mt], bf[nt]);
        }
        __syncthreads();
        if (++stg == 3) stg = 0;
    }

    int gid = lid >> 2, tig = lid & 3;
#pragma unroll
    for (int mt = 0; mt < 4; mt++) {
        int r0 = m0 + wm + mt * 16 + gid;
#pragma unroll
        for (int nt = 0; nt < 4; nt++) {
            int cc = n0 + wn + nt * 8 + tig * 2;
            float* a = acc[mt][nt];
#pragma unroll
            for (int half = 0; half < 2; half++) {
                int r = r0 + half * 8;
                float v0 = a[half * 2 + 0], v1 = a[half * 2 + 1];
                size_t o = (size_t)r * ldc + cc;
                if (EPI == 0) {
                    *(float2*)&C[o] = make_float2(v0, v1);
                } else if (EPI == 1) {
                    if (cc < N) { atomicAdd(&C[o], v0); atomicAdd(&C[o + 1], v1); }
                } else {
                    float b0 = aux[cc], b1 = aux[cc + 1];
                    float s0 = v0 + b0, s1 = v1 + b1;
                    s0 = (s0 > 20.f) ? s0 : log1pf(__expf(s0));
                    s1 = (s1 > 20.f) ? s1 : log1pf(__expf(s1));
                    *(float2*)&C[o] = make_float2(s0, s1);
                }
            }
        }
    }
}

// ---------------------------------------------------------------------------
// Depthwise causal conv (width 4) + bias + SiLU -> u (exact) + ur (tf32)
// ---------------------------------------------------------------------------
__global__ void conv_silu_kernel(const float* __restrict__ xz,
                                 const float* __restrict__ cw,
                                 const float* __restrict__ cb,
                                 float* __restrict__ u,
                                 float* __restrict__ ur)
{
    int idx = blockIdx.x * blockDim.x + threadIdx.x;
    if (idx >= MROWS * (DI_ / 4)) return;
    int i4 = idx % (DI_ / 4);
    int bt = idx / (DI_ / 4);
    int t  = bt % T_;
    int i  = i4 * 4;

    float4 w0 = ((const float4*)cw)[i + 0];
    float4 w1 = ((const float4*)cw)[i + 1];
    float4 w2 = ((const float4*)cw)[i + 2];
    float4 w3 = ((const float4*)cw)[i + 3];
    float4 bb = ((const float4*)cb)[i4];

    float4 x3 = (t >= 3) ? *(const float4*)&xz[(size_t)(bt - 3) * (2 * DI_) + i] : make_float4(0, 0, 0, 0);
    float4 x2 = (t >= 2) ? *(const float4*)&xz[(size_t)(bt - 2) * (2 * DI_) + i] : make_float4(0, 0, 0, 0);
    float4 x1 = (t >= 1) ? *(const float4*)&xz[(size_t)(bt - 1) * (2 * DI_) + i] : make_float4(0, 0, 0, 0);
    float4 x0 = *(const float4*)&xz[(size_t)bt * (2 * DI_) + i];

    float4 r;
    r.x = bb.x + w0.x * x3.x + w0.y * x2.x + w0.z * x1.x + w0.w * x0.x;
    r.y = bb.y + w1.x * x3.y + w1.y * x2.y + w1.z * x1.y + w1.w * x0.y;
    r.z = bb.z + w2.x * x3.z + w2.y * x2.z + w2.z * x1.z + w2.w * x0.z;
    r.w = bb.w + w3.x * x3.w + w3.y * x2.w + w3.z * x1.w + w3.w * x0.w;

    r.x = r.x / (1.f + __expf(-r.x));
    r.y = r.y / (1.f + __expf(-r.y));
    r.z = r.z / (1.f + __expf(-r.z));
    r.w = r.w / (1.f + __expf(-r.w));

    ((float4*)u)[idx] = r;
    ((float4*)ur)[idx] = rtf32_4(r);
}

// ---------------------------------------------------------------------------
// Selective scan: smem chunk staging with cp.async double buffering.
// Block = 16 channels x 16 states (256 thr). Chunks of 64 timesteps.
// Writes y tf32-rounded (only consumed by out_proj GEMM).
// ---------------------------------------------------------------------------
#define SCH 64
#define NCHK (T_ / SCH)

__global__ void __launch_bounds__(256)
scan_kernel(const float* __restrict__ delta,
            const float* __restrict__ u,
            const float* __restrict__ xdbc,
            const float* __restrict__ xz,
            const float* __restrict__ A_log,
            const float* __restrict__ Dp,
            float* __restrict__ y)
{
    int b  = blockIdx.x >> 7;
    int ib = blockIdx.x & 127;
    int i0 = ib * 16;
    int tid = threadIdx.x;
    int ci = tid >> 4;
    int s  = tid & 15;
    int i  = i0 + ci;

    __shared__ float sd[2][SCH][16];
    __shared__ float su[2][SCH][16];
    __shared__ float sB[2][SCH][16];
    __shared__ float sC[2][SCH][16];
    __shared__ float sz[2][SCH][16];
    __shared__ float sy[SCH][16];

    float a  = -__expf(A_log[i * DS_ + s]);
    float dp = Dp[i];
    float h  = 0.f;

    int lr = tid >> 2, lc = (tid & 3) * 4;

    auto load_chunk = [&](int stg, int t0) {
        size_t bt = (size_t)(b * T_ + t0 + lr);
        cp16(smem_u32(&sd[stg][lr][lc]), delta + bt * DI_ + i0 + lc, 16);
        cp16(smem_u32(&su[stg][lr][lc]), u + bt * DI_ + i0 + lc, 16);
        cp16(smem_u32(&sB[stg][lr][lc]), xdbc + bt * XDBC_ + R_ + lc, 16);
        cp16(smem_u32(&sC[stg][lr][lc]), xdbc + bt * XDBC_ + R_ + DS_ + lc, 16);
        cp16(smem_u32(&sz[stg][lr][lc]), xz + bt * (2 * DI_) + DI_ + i0 + lc, 16);
        cp_commit();
    };

    load_chunk(0, 0);

    for (int c = 0; c < NCHK; c++) {
        bool hasNext = (c + 1 < NCHK);
        if (hasNext) load_chunk((c + 1) & 1, (c + 1) * SCH);
        if (hasNext) cp_wait<1>(); else cp_wait<0>();
        __syncthreads();

        int stg = c & 1;
#pragma unroll 4
        for (int t = 0; t < SCH; t++) {
            float d  = sd[stg][t][ci];
            float uu = su[stg][t][ci];
            float Bv = sB[stg][t][s];
            float Cv = sC[stg][t][s];
            h = __expf(d * a) * h + (d * uu) * Bv;
            float p = h * Cv;
            p += __shfl_xor_sync(0xffffffffu, p, 8, 16);
            p += __shfl_xor_sync(0xffffffffu, p, 4, 16);
            p += __shfl_xor_sync(0xffffffffu, p, 2, 16);
            p += __shfl_xor_sync(0xffffffffu, p, 1, 16);
            if (s == 0) {
                float z = sz[stg][t][ci];
                sy[t][ci] = (p + uu * dp) * (z / (1.f + __expf(-z)));
            }
        }
        __syncthreads();

        {
            size_t bt = (size_t)(b * T_ + c * SCH + lr);
            float4 v = *(float4*)&sy[lr][lc];
            *(float4*)(y + bt * DI_ + i0 + lc) = rtf32_4(v);
        }
        __syncthreads();
    }
}

// ---------------------------------------------------------------------------
// Launch
// ---------------------------------------------------------------------------
extern "C" void kernel_launch(void* const* d_in, const int* in_sizes, int n_in,
                              void* d_out, int out_size)
{
    const float* x          = (const float*)d_in[0];
    const float* norm_w     = (const float*)d_in[1];
    const float* in_proj_w  = (const float*)d_in[2];
    const float* conv_w     = (const float*)d_in[3];
    const float* conv_b     = (const float*)d_in[4];
    const float* x_proj_w   = (const float*)d_in[5];
    const float* dt_proj_w  = (const float*)d_in[6];
    const float* dt_proj_b  = (const float*)d_in[7];
    const float* A_log      = (const float*)d_in[8];
    const float* D_param    = (const float*)d_in[9];
    const float* out_proj_w = (const float*)d_in[10];
    float* out = (float*)d_out;

    float *xz, *u, *ur, *xn, *xdbc, *delta, *y;
    float *win, *wout, *wxp, *wdt;
    cudaGetSymbolAddress((void**)&xz,    g_xz);
    cudaGetSymbolAddress((void**)&u,     g_u);
    cudaGetSymbolAddress((void**)&ur,    g_ur);
    cudaGetSymbolAddress((void**)&xn,    g_xn);
    cudaGetSymbolAddress((void**)&xdbc,  g_xdbc);
    cudaGetSymbolAddress((void**)&delta, g_delta);
    cudaGetSymbolAddress((void**)&y,     g_y);
    cudaGetSymbolAddress((void**)&win,   g_win);
    cudaGetSymbolAddress((void**)&wout,  g_wout);
    cudaGetSymbolAddress((void**)&wxp,   g_wxp);
    cudaGetSymbolAddress((void**)&wdt,   g_wdt);

    cudaFuncSetAttribute(gemm_tf32_kernel<0>, cudaFuncAttributeMaxDynamicSharedMemorySize, GSM);
    cudaFuncSetAttribute(gemm_tf32_kernel<1>, cudaFuncAttributeMaxDynamicSharedMemorySize, GSM);
    cudaFuncSetAttribute(gemm_tf32_kernel<3>, cudaFuncAttributeMaxDynamicSharedMemorySize, GSM);

    // 0. Round weights to tf32
    {
        int total = S0_ + S1_ + S2_ + S3_;
        round_weights_kernel<<<(total + 255) / 256, 256>>>(
            in_proj_w, win, out_proj_w, wout, x_proj_w, wxp, dt_proj_w, wdt);
    }

    // 1. RMSNorm -> xn (rounded)
    rmsnorm_kernel<<<MROWS, 256>>>(x, norm_w, xn);

    // 2. in_proj: xz[2048,4096] = xn @ W^T   (512 CTAs)
    gemm_tf32_kernel<0><<<dim3(2 * DI_ / 128, MROWS / 128, 1), 256, GSM>>>(
        xn, D_, win, D_, nullptr, xz, 2 * DI_, 2 * DI_, D_);

    // 3. conv + silu -> u (exact) + ur (rounded)
    conv_silu_kernel<<<(MROWS * DI_ / 4 + 255) / 256, 256>>>(xz, conv_w, conv_b, u, ur);

    // 4. x_proj: xdbc = ur @ W^T (split-K=16, atomics; 256 CTAs)
    cudaMemsetAsync(xdbc, 0, (size_t)MROWS * XDBC_ * sizeof(float));
    gemm_tf32_kernel<1><<<dim3(1, MROWS / 128, 16), 256, GSM>>>(
        ur, DI_, wxp, DI_, nullptr, xdbc, XDBC_, XDBC_, DI_ / 16);

    // 5. dt_proj + softplus: delta[2048,2048] (256 CTAs)
    gemm_tf32_kernel<3><<<dim3(DI_ / 128, MROWS / 128, 1), 256, GSM>>>(
        xdbc, XDBC_, wdt, R_, dt_proj_b, delta, DI_, DI_, R_);

    // 6. selective scan (fused gate + skip) -> y (rounded)
    scan_kernel<<<B_ * (DI_ / 16), 256>>>(delta, u, xdbc, xz, A_log, D_param, y);

    // 7. out_proj + residual: prefill out with residual, split-K=2 atomicAdd (256 CTAs)
    copy_kernel<<<(MROWS * D_ / 4 + 255) / 256, 256>>>(x, out, MROWS * D_ / 4);
    gemm_tf32_kernel<1><<<dim3(D_ / 128, MROWS / 128, 2), 256, GSM>>>(
        y, DI_, wout, DI_, nullptr, out, D_, D_, DI_ / 2);
}

// round 10
// speedup vs baseline: 3.7284x; 1.0143x over previous
#include <cuda_runtime.h>
#include <cuda_bf16.h>
#include <math.h>
#include <stdint.h>

// Problem dims
#define B_   2
#define T_   1024
#define D_   1024
#define DI_  2048          // D_INNER
#define DS_  16            // D_STATE
#define R_   64            // DT_RANK
#define XDBC_ 96           // R_ + 2*DS_
#define MROWS (B_*T_)      // 2048

// ---------------------------------------------------------------------------
// Scratch (device globals; no allocation allowed)
// ---------------------------------------------------------------------------
__device__ __align__(256) float g_xz[MROWS * 2 * DI_];     // in_proj out
__device__ __align__(256) float g_u[MROWS * DI_];          // conv out (tf32-rounded)
__device__ __align__(256) float g_xn[MROWS * D_];          // rmsnorm out (rounded)
__device__ __align__(256) float g_xdbc[MROWS * XDBC_];     // x_proj out
__device__ __align__(256) float g_delta[MROWS * DI_];      // dt_proj out
__device__ __align__(256) float g_y[MROWS * DI_];          // scan out (rounded)
__device__ __align__(256) float g_win[2 * DI_ * D_];       // tf32-rounded weights
__device__ __align__(256) float g_wout[D_ * DI_];
__device__ __align__(256) float g_wxp[XDBC_ * DI_];
__device__ __align__(256) float g_wdt[DI_ * R_];

// ---------------------------------------------------------------------------
// Helpers
// ---------------------------------------------------------------------------
__device__ __forceinline__ uint32_t smem_u32(const void* p) {
    uint32_t a;
    asm("{ .reg .u64 t; cvta.to.shared.u64 t, %1; cvt.u32.u64 %0, t; }" : "=r"(a) : "l"(p));
    return a;
}
__device__ __forceinline__ uint32_t sw128(uint32_t b) { return b ^ ((b >> 3) & 0x70); }

__device__ __forceinline__ void cp16(uint32_t smem, const void* gmem, int srcBytes) {
    asm volatile("cp.async.cg.shared.global [%0], [%1], 16, %2;"
                 :: "r"(smem), "l"(gmem), "r"(srcBytes));
}
__device__ __forceinline__ void cp_commit() {
    asm volatile("cp.async.commit_group;" ::: "memory");
}
template<int N>
__device__ __forceinline__ void cp_wait() {
    asm volatile("cp.async.wait_group %0;" :: "n"(N) : "memory");
}

__device__ __forceinline__ void ldsm_x4(uint32_t* r, uint32_t addr) {
    asm volatile("ldmatrix.sync.aligned.m8n8.x4.shared.b16 {%0,%1,%2,%3}, [%4];"
                 : "=r"(r[0]), "=r"(r[1]), "=r"(r[2]), "=r"(r[3]) : "r"(addr));
}
__device__ __forceinline__ void mma_tf32(float* c, const uint32_t* a, const uint32_t* b) {
    asm volatile("mma.sync.aligned.m16n8k8.row.col.f32.tf32.tf32.f32 "
                 "{%0,%1,%2,%3}, {%4,%5,%6,%7}, {%8,%9}, {%0,%1,%2,%3};"
                 : "+f"(c[0]), "+f"(c[1]), "+f"(c[2]), "+f"(c[3])
                 : "r"(a[0]), "r"(a[1]), "r"(a[2]), "r"(a[3]), "r"(b[0]), "r"(b[1]));
}

__device__ __forceinline__ float rtf32(float x) {
    float r;
    asm("cvt.rna.tf32.f32 %0, %1;" : "=f"(r) : "f"(x));
    return r;
}
__device__ __forceinline__ float4 rtf32_4(float4 v) {
    v.x = rtf32(v.x); v.y = rtf32(v.y); v.z = rtf32(v.z); v.w = rtf32(v.w);
    return v;
}

// ---------------------------------------------------------------------------
// Round all weights to tf32 (fused, float4-vectorized)
// ---------------------------------------------------------------------------
#define S0_ (2 * DI_ * D_ / 4)
#define S1_ (D_ * DI_ / 4)
#define S2_ (XDBC_ * DI_ / 4)
#define S3_ (DI_ * R_ / 4)

__global__ void round_weights_kernel(
    const float* __restrict__ w0, float* __restrict__ o0,
    const float* __restrict__ w1, float* __restrict__ o1,
    const float* __restrict__ w2, float* __restrict__ o2,
    const float* __restrict__ w3, float* __restrict__ o3)
{
    int i = blockIdx.x * blockDim.x + threadIdx.x;
    const float* src; float* dst; int off;
    if (i < S0_)                        { src = w0; dst = o0; off = i; }
    else if (i < S0_ + S1_)             { src = w1; dst = o1; off = i - S0_; }
    else if (i < S0_ + S1_ + S2_)       { src = w2; dst = o2; off = i - S0_ - S1_; }
    else if (i < S0_ + S1_ + S2_ + S3_) { src = w3; dst = o3; off = i - S0_ - S1_ - S2_; }
    else return;
    ((float4*)dst)[off] = rtf32_4(((const float4*)src)[off]);
}

__global__ void copy_kernel(const float* __restrict__ src, float* __restrict__ dst, int n4)
{
    int i = blockIdx.x * blockDim.x + threadIdx.x;
    if (i < n4) ((float4*)dst)[i] = ((const float4*)src)[i];
}

// ---------------------------------------------------------------------------
// RMSNorm -> tf32-rounded f32
// ---------------------------------------------------------------------------
__global__ void rmsnorm_kernel(const float* __restrict__ x,
                               const float* __restrict__ w,
                               float* __restrict__ o)
{
    int row = blockIdx.x;
    const float* xr = x + (size_t)row * D_;
    float s = 0.f;
    for (int i = threadIdx.x; i < D_ / 4; i += 256) {
        float4 v = ((const float4*)xr)[i];
        s += v.x * v.x + v.y * v.y + v.z * v.z + v.w * v.w;
    }
    __shared__ float red[8];
    for (int off = 16; off; off >>= 1) s += __shfl_xor_sync(0xffffffffu, s, off);
    if ((threadIdx.x & 31) == 0) red[threadIdx.x >> 5] = s;
    __syncthreads();
    if (threadIdx.x < 8) {
        float t = red[threadIdx.x];
        t += __shfl_xor_sync(0xffu, t, 4);
        t += __shfl_xor_sync(0xffu, t, 2);
        t += __shfl_xor_sync(0xffu, t, 1);
        if (threadIdx.x == 0) red[0] = t;
    }
    __syncthreads();
    float scale = rsqrtf(red[0] * (1.f / D_) + 1.1920929e-7f);
    for (int i = threadIdx.x; i < D_ / 4; i += 256) {
        float4 v = ((const float4*)xr)[i];
        float4 wv = ((const float4*)w)[i];
        v.x *= scale * wv.x; v.y *= scale * wv.y;
        v.z *= scale * wv.z; v.w *= scale * wv.w;
        ((float4*)(o + (size_t)row * D_))[i] = rtf32_4(v);
    }
}

// ---------------------------------------------------------------------------
// tf32 tensor-core GEMM:
//   C[M, N(ldc)] (op)= A[M,*](lda) @ W[N,*](ldb)^T over K slice [z*kLen, +kLen)
// 128x128 CTA tile, BK=32, 256 threads (8 warps 2x4), warp tile 64x32.
// 3-stage cp.async pipeline (32KB/stage, 2 CTAs/SM).
// EPI: 0 = store, 1 = atomicAdd (split-K), 3 = softplus(v + bias[n])
// ---------------------------------------------------------------------------
#define GSTG 32768
#define GSM  (3 * GSTG)

template<int EPI>
__global__ void __launch_bounds__(256, 2)
gemm_tf32_kernel(const float* __restrict__ A, int lda,
                 const float* __restrict__ Bm, int ldb,
                 const float* __restrict__ aux, float* __restrict__ C,
                 int N, int ldc, int kLen)
{
    extern __shared__ char smem[];
    uint32_t sb = smem_u32(smem);
    int tid = threadIdx.x, wid = tid >> 5, lid = tid & 31;
    int m0 = blockIdx.y * 128, n0 = blockIdx.x * 128;
    int kStart = blockIdx.z * kLen;
    int bRows = N - n0; if (bRows > 128) bRows = 128;
    int wm = (wid >> 2) * 64, wn = (wid & 3) * 32;

    float acc[4][4][4];
#pragma unroll
    for (int i = 0; i < 4; i++)
#pragma unroll
        for (int j = 0; j < 4; j++)
#pragma unroll
            for (int k = 0; k < 4; k++) acc[i][j][k] = 0.f;

    int nCh = kLen / 32;

    auto load_chunk = [&](int s, int k0) {
        uint32_t st = sb + s * GSTG;
#pragma unroll
        for (int p = 0; p < 4; p++) {
            int idx = tid + p * 256;
            int r = idx >> 3, c = idx & 7;
            uint32_t so = sw128((uint32_t)(r * 128 + c * 16));
            cp16(st + so, A + (size_t)(m0 + r) * lda + k0 + c * 4, 16);
        }
#pragma unroll
        for (int p = 0; p < 4; p++) {
            int idx = tid + p * 256;
            int r = idx >> 3, c = idx & 7;
            uint32_t so = sw128((uint32_t)(r * 128 + c * 16));
            int rb = (r < bRows) ? r : (bRows - 1);
            int ok = (r < bRows) ? 16 : 0;
            cp16(st + 16384 + so, Bm + (size_t)(n0 + rb) * ldb + k0 + c * 4, ok);
        }
        cp_commit();
    };

    load_chunk(0, kStart);
    if (nCh > 1) load_chunk(1, kStart + 32);

    int stg = 0;
    for (int ch = 0; ch < nCh; ch++) {
        if (ch + 2 < nCh) {
            int s2 = stg + 2; if (s2 >= 3) s2 -= 3;
            load_chunk(s2, kStart + (ch + 2) * 32);
            cp_wait<2>();
        } else if (ch + 1 < nCh) {
            cp_wait<1>();
        } else {
            cp_wait<0>();
        }
        __syncthreads();

        uint32_t stA = sb + stg * GSTG;
        uint32_t stB = stA + 16384;
#pragma unroll
        for (int ksp = 0; ksp < 2; ksp++) {     // pair of k8 steps
            // B fragments for both k8 steps of the pair: one ldsm_x4 per nt.
            // lanes 0-7 -> (row, cb+0), 8-15 -> cb+1, 16-23 -> cb+2, 24-31 -> cb+3
            uint32_t bf[4][4];
            int cb = ksp * 4;
#pragma unroll
            for (int nt = 0; nt < 4; nt++) {
                int row = wn + nt * 8 + (lid & 7);
                int chunk = cb + (lid >> 3);
                ldsm_x4(bf[nt], stB + sw128((uint32_t)(row * 128 + chunk * 16)));
            }
#pragma unroll
            for (int ks2 = 0; ks2 < 2; ks2++) {
                int ks = ksp * 2 + ks2;
                uint32_t af[4][4];
#pragma unroll
                for (int mt = 0; mt < 4; mt++) {
                    int row = wm + mt * 16 + (lid & 15);
                    int chunk = ks * 2 + (lid >> 4);
                    ldsm_x4(af[mt], stA + sw128((uint32_t)(row * 128 + chunk * 16)));
                }
#pragma unroll
                for (int mt = 0; mt < 4; mt++)
#pragma unroll
                    for (int nt = 0; nt < 4; nt++)
                        mma_tf32(acc[mt][nt], af[mt], bf[nt] + ks2 * 2);
            }
        }
        __syncthreads();
        if (++stg == 3) stg = 0;
    }

    int gid = lid >> 2, tig = lid & 3;
#pragma unroll
    for (int mt = 0; mt < 4; mt++) {
        int r0 = m0 + wm + mt * 16 + gid;
#pragma unroll
        for (int nt = 0; nt < 4; nt++) {
            int cc = n0 + wn + nt * 8 + tig * 2;
            float* a = acc[mt][nt];
#pragma unroll
            for (int half = 0; half < 2; half++) {
                int r = r0 + half * 8;
                float v0 = a[half * 2 + 0], v1 = a[half * 2 + 1];
                size_t o = (size_t)r * ldc + cc;
                if (EPI == 0) {
                    *(float2*)&C[o] = make_float2(v0, v1);
                } else if (EPI == 1) {
                    if (cc < N) { atomicAdd(&C[o], v0); atomicAdd(&C[o + 1], v1); }
                } else {
                    float b0 = aux[cc], b1 = aux[cc + 1];
                    float s0 = v0 + b0, s1 = v1 + b1;
                    s0 = (s0 > 20.f) ? s0 : log1pf(__expf(s0));
                    s1 = (s1 > 20.f) ? s1 : log1pf(__expf(s1));
                    *(float2*)&C[o] = make_float2(s0, s1);
                }
            }
        }
    }
}

// ---------------------------------------------------------------------------
// Depthwise causal conv (width 4) + bias + SiLU -> u (tf32-rounded, single out)
// ---------------------------------------------------------------------------
__global__ void conv_silu_kernel(const float* __restrict__ xz,
                                 const float* __restrict__ cw,
                                 const float* __restrict__ cb,
                                 float* __restrict__ u)
{
    int idx = blockIdx.x * blockDim.x + threadIdx.x;
    if (idx >= MROWS * (DI_ / 4)) return;
    int i4 = idx % (DI_ / 4);
    int bt = idx / (DI_ / 4);
    int t  = bt % T_;
    int i  = i4 * 4;

    float4 w0 = ((const float4*)cw)[i + 0];
    float4 w1 = ((const float4*)cw)[i + 1];
    float4 w2 = ((const float4*)cw)[i + 2];
    float4 w3 = ((const float4*)cw)[i + 3];
    float4 bb = ((const float4*)cb)[i4];

    float4 x3 = (t >= 3) ? *(const float4*)&xz[(size_t)(bt - 3) * (2 * DI_) + i] : make_float4(0, 0, 0, 0);
    float4 x2 = (t >= 2) ? *(const float4*)&xz[(size_t)(bt - 2) * (2 * DI_) + i] : make_float4(0, 0, 0, 0);
    float4 x1 = (t >= 1) ? *(const float4*)&xz[(size_t)(bt - 1) * (2 * DI_) + i] : make_float4(0, 0, 0, 0);
    float4 x0 = *(const float4*)&xz[(size_t)bt * (2 * DI_) + i];

    float4 r;
    r.x = bb.x + w0.x * x3.x + w0.y * x2.x + w0.z * x1.x + w0.w * x0.x;
    r.y = bb.y + w1.x * x3.y + w1.y * x2.y + w1.z * x1.y + w1.w * x0.y;
    r.z = bb.z + w2.x * x3.z + w2.y * x2.z + w2.z * x1.z + w2.w * x0.z;
    r.w = bb.w + w3.x * x3.w + w3.y * x2.w + w3.z * x1.w + w3.w * x0.w;

    r.x = r.x / (1.f + __expf(-r.x));
    r.y = r.y / (1.f + __expf(-r.y));
    r.z = r.z / (1.f + __expf(-r.z));
    r.w = r.w / (1.f + __expf(-r.w));

    ((float4*)u)[idx] = rtf32_4(r);
}

// ---------------------------------------------------------------------------
// Selective scan: smem chunk staging with cp.async double buffering.
// Block = 16 channels x 16 states (256 thr). Chunks of 64 timesteps.
// ---------------------------------------------------------------------------
#define SCH 64
#define NCHK (T_ / SCH)

__global__ void __launch_bounds__(256)
scan_kernel(const float* __restrict__ delta,
            const float* __restrict__ u,
            const float* __restrict__ xdbc,
            const float* __restrict__ xz,
            const float* __restrict__ A_log,
            const float* __restrict__ Dp,
            float* __restrict__ y)
{
    int b  = blockIdx.x >> 7;
    int ib = blockIdx.x & 127;
    int i0 = ib * 16;
    int tid = threadIdx.x;
    int ci = tid >> 4;
    int s  = tid & 15;
    int i  = i0 + ci;

    __shared__ float sd[2][SCH][16];
    __shared__ float su[2][SCH][16];
    __shared__ float sB[2][SCH][16];
    __shared__ float sC[2][SCH][16];
    __shared__ float sz[2][SCH][16];
    __shared__ float sy[SCH][16];

    float a  = -__expf(A_log[i * DS_ + s]);
    float dp = Dp[i];
    float h  = 0.f;

    int lr = tid >> 2, lc = (tid & 3) * 4;

    auto load_chunk = [&](int stg, int t0) {
        size_t bt = (size_t)(b * T_ + t0 + lr);
        cp16(smem_u32(&sd[stg][lr][lc]), delta + bt * DI_ + i0 + lc, 16);
        cp16(smem_u32(&su[stg][lr][lc]), u + bt * DI_ + i0 + lc, 16);
        cp16(smem_u32(&sB[stg][lr][lc]), xdbc + bt * XDBC_ + R_ + lc, 16);
        cp16(smem_u32(&sC[stg][lr][lc]), xdbc + bt * XDBC_ + R_ + DS_ + lc, 16);
        cp16(smem_u32(&sz[stg][lr][lc]), xz + bt * (2 * DI_) + DI_ + i0 + lc, 16);
        cp_commit();
    };

    load_chunk(0, 0);

    for (int c = 0; c < NCHK; c++) {
        bool hasNext = (c + 1 < NCHK);
        if (hasNext) load_chunk((c + 1) & 1, (c + 1) * SCH);
        if (hasNext) cp_wait<1>(); else cp_wait<0>();
        __syncthreads();

        int stg = c & 1;
#pragma unroll 4
        for (int t = 0; t < SCH; t++) {
            float d  = sd[stg][t][ci];
            float uu = su[stg][t][ci];
            float Bv = sB[stg][t][s];
            float Cv = sC[stg][t][s];
            h = __expf(d * a) * h + (d * uu) * Bv;
            float p = h * Cv;
            p += __shfl_xor_sync(0xffffffffu, p, 8, 16);
            p += __shfl_xor_sync(0xffffffffu, p, 4, 16);
            p += __shfl_xor_sync(0xffffffffu, p, 2, 16);
            p += __shfl_xor_sync(0xffffffffu, p, 1, 16);
            if (s == 0) {
                float z = sz[stg][t][ci];
                sy[t][ci] = (p + uu * dp) * (z / (1.f + __expf(-z)));
            }
        }
        __syncthreads();

        {
            size_t bt = (size_t)(b * T_ + c * SCH + lr);
            float4 v = *(float4*)&sy[lr][lc];
            *(float4*)(y + bt * DI_ + i0 + lc) = rtf32_4(v);
        }
        __syncthreads();
    }
}

// ---------------------------------------------------------------------------
// Launch
// ---------------------------------------------------------------------------
extern "C" void kernel_launch(void* const* d_in, const int* in_sizes, int n_in,
                              void* d_out, int out_size)
{
    const float* x          = (const float*)d_in[0];
    const float* norm_w     = (const float*)d_in[1];
    const float* in_proj_w  = (const float*)d_in[2];
    const float* conv_w     = (const float*)d_in[3];
    const float* conv_b     = (const float*)d_in[4];
    const float* x_proj_w   = (const float*)d_in[5];
    const float* dt_proj_w  = (const float*)d_in[6];
    const float* dt_proj_b  = (const float*)d_in[7];
    const float* A_log      = (const float*)d_in[8];
    const float* D_param    = (const float*)d_in[9];
    const float* out_proj_w = (const float*)d_in[10];
    float* out = (float*)d_out;

    float *xz, *u, *xn, *xdbc, *delta, *y;
    float *win, *wout, *wxp, *wdt;
    cudaGetSymbolAddress((void**)&xz,    g_xz);
    cudaGetSymbolAddress((void**)&u,     g_u);
    cudaGetSymbolAddress((void**)&xn,    g_xn);
    cudaGetSymbolAddress((void**)&xdbc,  g_xdbc);
    cudaGetSymbolAddress((void**)&delta, g_delta);
    cudaGetSymbolAddress((void**)&y,     g_y);
    cudaGetSymbolAddress((void**)&win,   g_win);
    cudaGetSymbolAddress((void**)&wout,  g_wout);
    cudaGetSymbolAddress((void**)&wxp,   g_wxp);
    cudaGetSymbolAddress((void**)&wdt,   g_wdt);

    cudaFuncSetAttribute(gemm_tf32_kernel<0>, cudaFuncAttributeMaxDynamicSharedMemorySize, GSM);
    cudaFuncSetAttribute(gemm_tf32_kernel<1>, cudaFuncAttributeMaxDynamicSharedMemorySize, GSM);
    cudaFuncSetAttribute(gemm_tf32_kernel<3>, cudaFuncAttributeMaxDynamicSharedMemorySize, GSM);

    // #0: round weights to tf32
    {
        int total = S0_ + S1_ + S2_ + S3_;
        round_weights_kernel<<<(total + 255) / 256, 256>>>(
            in_proj_w, win, out_proj_w, wout, x_proj_w, wxp, dt_proj_w, wdt);
    }

    // #1: RMSNorm -> xn (rounded)
    rmsnorm_kernel<<<MROWS, 256>>>(x, norm_w, xn);

    // #2: prefill out with residual (independent; also positions in_proj at #3)
    copy_kernel<<<(MROWS * D_ / 4 + 255) / 256, 256>>>(x, out, MROWS * D_ / 4);

    // #3: in_proj: xz[2048,4096] = xn @ W^T   (512 CTAs)  <-- ncu captures this
    gemm_tf32_kernel<0><<<dim3(2 * DI_ / 128, MROWS / 128, 1), 256, GSM>>>(
        xn, D_, win, D_, nullptr, xz, 2 * DI_, 2 * DI_, D_);

    // #4: conv + silu -> u (rounded, single output)
    conv_silu_kernel<<<(MROWS * DI_ / 4 + 255) / 256, 256>>>(xz, conv_w, conv_b, u);

    // #5: x_proj: xdbc = u @ W^T (split-K=8, atomics; 128 CTAs)
    cudaMemsetAsync(xdbc, 0, (size_t)MROWS * XDBC_ * sizeof(float));
    gemm_tf32_kernel<1><<<dim3(1, MROWS / 128, 8), 256, GSM>>>(
        u, DI_, wxp, DI_, nullptr, xdbc, XDBC_, XDBC_, DI_ / 8);

    // #6: dt_proj + softplus: delta[2048,2048] (256 CTAs)
    gemm_tf32_kernel<3><<<dim3(DI_ / 128, MROWS / 128, 1), 256, GSM>>>(
        xdbc, XDBC_, wdt, R_, dt_proj_b, delta, DI_, DI_, R_);

    // #7: selective scan (fused gate + skip) -> y (rounded)
    scan_kernel<<<B_ * (DI_ / 16), 256>>>(delta, u, xdbc, xz, A_log, D_param, y);

    // #8: out_proj + residual: split-K=2 atomicAdd into prefilled out (256 CTAs)
    gemm_tf32_kernel<1><<<dim3(D_ / 128, MROWS / 128, 2), 256, GSM>>>(
        y, DI_, wout, DI_, nullptr, out, D_, D_, DI_ / 2);
}

// round 12
// speedup vs baseline: 4.5253x; 1.2137x over previous
#include <cuda_runtime.h>
#include <cuda_fp16.h>
#include <math.h>
#include <stdint.h>

// Problem dims
#define B_   2
#define T_   1024
#define D_   1024
#define DI_  2048          // D_INNER
#define DS_  16            // D_STATE
#define R_   64            // DT_RANK
#define XDBC_ 96           // R_ + 2*DS_
#define MROWS (B_*T_)      // 2048

// ---------------------------------------------------------------------------
// Scratch (device globals; no allocation allowed)
// ---------------------------------------------------------------------------
__device__ __align__(256) float g_xz[MROWS * 2 * DI_];     // in_proj out (f32)
__device__ __align__(256) float g_u[MROWS * DI_];          // conv out f32 (scan)
__device__ __align__(256) float g_xdbc[MROWS * XDBC_];     // x_proj out (f32)
__device__ __align__(256) float g_delta[MROWS * DI_];      // dt_proj out (f32)

__device__ __align__(256) __half g_xnh[MROWS * D_];        // rmsnorm out
__device__ __align__(256) __half g_uh[MROWS * DI_];        // conv out (GEMM input)
__device__ __align__(256) __half g_yh[MROWS * DI_];        // scan out
__device__ __align__(256) __half g_xdbch[MROWS * XDBC_];   // xdbc (dt_proj input)
__device__ __align__(256) __half g_winh[2 * DI_ * D_];
__device__ __align__(256) __half g_wouth[D_ * DI_];
__device__ __align__(256) __half g_wxph[XDBC_ * DI_];
__device__ __align__(256) __half g_wdth[DI_ * R_];

// ---------------------------------------------------------------------------
// Helpers
// ---------------------------------------------------------------------------
__device__ __forceinline__ uint32_t smem_u32(const void* p) {
    uint32_t a;
    asm("{ .reg .u64 t; cvta.to.shared.u64 t, %1; cvt.u32.u64 %0, t; }" : "=r"(a) : "l"(p));
    return a;
}
__device__ __forceinline__ uint32_t sw128(uint32_t b) { return b ^ ((b >> 3) & 0x70); }

__device__ __forceinline__ void cp16(uint32_t smem, const void* gmem, int srcBytes) {
    asm volatile("cp.async.cg.shared.global [%0], [%1], 16, %2;"
                 :: "r"(smem), "l"(gmem), "r"(srcBytes));
}
__device__ __forceinline__ void cp_commit() {
    asm volatile("cp.async.commit_group;" ::: "memory");
}
template<int N>
__device__ __forceinline__ void cp_wait() {
    asm volatile("cp.async.wait_group %0;" :: "n"(N) : "memory");
}

__device__ __forceinline__ void ldsm_x4(uint32_t* r, uint32_t addr) {
    asm volatile("ldmatrix.sync.aligned.m8n8.x4.shared.b16 {%0,%1,%2,%3}, [%4];"
                 : "=r"(r[0]), "=r"(r[1]), "=r"(r[2]), "=r"(r[3]) : "r"(addr));
}
// fp16 m16n8k16 MMA, f32 accumulate
__device__ __forceinline__ void mma_fp16(float* c, const uint32_t* a, const uint32_t* b) {
    asm volatile("mma.sync.aligned.m16n8k16.row.col.f32.f16.f16.f32 "
                 "{%0,%1,%2,%3}, {%4,%5,%6,%7}, {%8,%9}, {%0,%1,%2,%3};"
                 : "+f"(c[0]), "+f"(c[1]), "+f"(c[2]), "+f"(c[3])
                 : "r"(a[0]), "r"(a[1]), "r"(a[2]), "r"(a[3]), "r"(b[0]), "r"(b[1]));
}

// pack 4 f32 -> 4 fp16 (uint2)
__device__ __forceinline__ uint2 h4(float4 v) {
    __half2 a = __floats2half2_rn(v.x, v.y);
    __half2 b = __floats2half2_rn(v.z, v.w);
    return make_uint2(*(uint32_t*)&a, *(uint32_t*)&b);
}

// ---------------------------------------------------------------------------
// Convert all weights to fp16 (fused, float4-vectorized)
// ---------------------------------------------------------------------------
#define S0_ (2 * DI_ * D_ / 4)
#define S1_ (D_ * DI_ / 4)
#define S2_ (XDBC_ * DI_ / 4)
#define S3_ (DI_ * R_ / 4)

__global__ void cvt_weights_kernel(
    const float* __restrict__ w0, __half* __restrict__ o0,
    const float* __restrict__ w1, __half* __restrict__ o1,
    const float* __restrict__ w2, __half* __restrict__ o2,
    const float* __restrict__ w3, __half* __restrict__ o3)
{
    int i = blockIdx.x * blockDim.x + threadIdx.x;
    const float* src; __half* dst; int off;
    if (i < S0_)                        { src = w0; dst = o0; off = i; }
    else if (i < S0_ + S1_)             { src = w1; dst = o1; off = i - S0_; }
    else if (i < S0_ + S1_ + S2_)       { src = w2; dst = o2; off = i - S0_ - S1_; }
    else if (i < S0_ + S1_ + S2_ + S3_) { src = w3; dst = o3; off = i - S0_ - S1_ - S2_; }
    else return;
    ((uint2*)dst)[off] = h4(((const float4*)src)[off]);
}

__global__ void cvt_kernel(const float* __restrict__ src, __half* __restrict__ dst, int n4)
{
    int i = blockIdx.x * blockDim.x + threadIdx.x;
    if (i < n4) ((uint2*)dst)[i] = h4(((const float4*)src)[i]);
}

__global__ void copy_kernel(const float* __restrict__ src, float* __restrict__ dst, int n4)
{
    int i = blockIdx.x * blockDim.x + threadIdx.x;
    if (i < n4) ((float4*)dst)[i] = ((const float4*)src)[i];
}

// ---------------------------------------------------------------------------
// RMSNorm -> fp16
// ---------------------------------------------------------------------------
__global__ void rmsnorm_kernel(const float* __restrict__ x,
                               const float* __restrict__ w,
                               __half* __restrict__ o)
{
    int row = blockIdx.x;
    const float* xr = x + (size_t)row * D_;
    float s = 0.f;
    for (int i = threadIdx.x; i < D_ / 4; i += 256) {
        float4 v = ((const float4*)xr)[i];
        s += v.x * v.x + v.y * v.y + v.z * v.z + v.w * v.w;
    }
    __shared__ float red[8];
    for (int off = 16; off; off >>= 1) s += __shfl_xor_sync(0xffffffffu, s, off);
    if ((threadIdx.x & 31) == 0) red[threadIdx.x >> 5] = s;
    __syncthreads();
    if (threadIdx.x < 8) {
        float t = red[threadIdx.x];
        t += __shfl_xor_sync(0xffu, t, 4);
        t += __shfl_xor_sync(0xffu, t, 2);
        t += __shfl_xor_sync(0xffu, t, 1);
        if (threadIdx.x == 0) red[0] = t;
    }
    __syncthreads();
    float scale = rsqrtf(red[0] * (1.f / D_) + 1.1920929e-7f);
    for (int i = threadIdx.x; i < D_ / 4; i += 256) {
        float4 v = ((const float4*)xr)[i];
        float4 wv = ((const float4*)w)[i];
        v.x *= scale * wv.x; v.y *= scale * wv.y;
        v.z *= scale * wv.z; v.w *= scale * wv.w;
        ((uint2*)(o + (size_t)row * D_))[i] = h4(v);
    }
}

// ---------------------------------------------------------------------------
// fp16 tensor-core GEMM:
//   C[M, N(ldc)] (op)= A[M,*](lda) @ W[N,*](ldb)^T over K slice [z*kLen, +kLen)
// 128x128 CTA tile, BK=64 (fp16, 128B rows, SW128), 256 threads (8 warps 2x4),
// warp tile 64x32. 3-stage cp.async pipeline (32KB/stage -> 2 CTAs/SM).
// EPI: 0 = store, 1 = atomicAdd (split-K), 3 = softplus(v + bias[n])
// ---------------------------------------------------------------------------
#define GSTG 32768
#define GSM  (3 * GSTG)

template<int EPI>
__global__ void __launch_bounds__(256, 2)
gemm_fp16_kernel(const __half* __restrict__ A, int lda,
                 const __half* __restrict__ Bm, int ldb,
                 const float* __restrict__ aux, float* __restrict__ C,
                 int N, int ldc, int kLen)
{
    extern __shared__ char smem[];
    uint32_t sb = smem_u32(smem);
    int tid = threadIdx.x, wid = tid >> 5, lid = tid & 31;
    int m0 = blockIdx.y * 128, n0 = blockIdx.x * 128;
    int kStart = blockIdx.z * kLen;
    int bRows = N - n0; if (bRows > 128) bRows = 128;
    int wm = (wid >> 2) * 64, wn = (wid & 3) * 32;

    float acc[4][4][4];
#pragma unroll
    for (int i = 0; i < 4; i++)
#pragma unroll
        for (int j = 0; j < 4; j++)
#pragma unroll
            for (int k = 0; k < 4; k++) acc[i][j][k] = 0.f;

    int nCh = kLen / 64;

    auto load_chunk = [&](int s, int k0) {
        uint32_t st = sb + s * GSTG;
        // A: 128 rows x 128B (64 fp16)
#pragma unroll
        for (int p = 0; p < 4; p++) {
            int idx = tid + p * 256;
            int r = idx >> 3, c = idx & 7;
            uint32_t so = sw128((uint32_t)(r * 128 + c * 16));
            cp16(st + so, A + (size_t)(m0 + r) * lda + k0 + c * 8, 16);
        }
        // B: 128 rows x 128B
#pragma unroll
        for (int p = 0; p < 4; p++) {
            int idx = tid + p * 256;
            int r = idx >> 3, c = idx & 7;
            uint32_t so = sw128((uint32_t)(r * 128 + c * 16));
            int rb = (r < bRows) ? r : (bRows - 1);
            int ok = (r < bRows) ? 16 : 0;
            cp16(st + 16384 + so, Bm + (size_t)(n0 + rb) * ldb + k0 + c * 8, ok);
        }
        cp_commit();
    };

    load_chunk(0, kStart);
    if (nCh > 1) load_chunk(1, kStart + 64);

    int stg = 0;
    for (int ch = 0; ch < nCh; ch++) {
        if (ch + 2 < nCh) {
            int s2 = stg + 2; if (s2 >= 3) s2 -= 3;
            load_chunk(s2, kStart + (ch + 2) * 64);
            cp_wait<2>();
        } else if (ch + 1 < nCh) {
            cp_wait<1>();
        } else {
            cp_wait<0>();
        }
        __syncthreads();

        uint32_t stA = sb + stg * GSTG;
        uint32_t stB = stA + 16384;
#pragma unroll
        for (int ksp = 0; ksp < 2; ksp++) {     // pair of k16 steps
            // B: one ldsm_x4 per nt covers both k16 steps of the pair
            uint32_t bf[4][4];
            int cb = ksp * 4;
#pragma unroll
            for (int nt = 0; nt < 4; nt++) {
                int row = wn + nt * 8 + (lid & 7);
                int chunk = cb + (lid >> 3);
                ldsm_x4(bf[nt], stB + sw128((uint32_t)(row * 128 + chunk * 16)));
            }
#pragma unroll
            for (int ks2 = 0; ks2 < 2; ks2++) {
                int ks = ksp * 2 + ks2;         // k16 index 0..3
                uint32_t af[4][4];
#pragma unroll
                for (int mt = 0; mt < 4; mt++) {
                    int row = wm + mt * 16 + (lid & 15);
                    int chunk = ks * 2 + (lid >> 4);
                    ldsm_x4(af[mt], stA + sw128((uint32_t)(row * 128 + chunk * 16)));
                }
#pragma unroll
                for (int mt = 0; mt < 4; mt++)
#pragma unroll
                    for (int nt = 0; nt < 4; nt++)
                        mma_fp16(acc[mt][nt], af[mt], bf[nt] + ks2 * 2);
            }
        }
        __syncthreads();
        if (++stg == 3) stg = 0;
    }

    int gid = lid >> 2, tig = lid & 3;
#pragma unroll
    for (int mt = 0; mt < 4; mt++) {
        int r0 = m0 + wm + mt * 16 + gid;
#pragma unroll
        for (int nt = 0; nt < 4; nt++) {
            int cc = n0 + wn + nt * 8 + tig * 2;
            float* a = acc[mt][nt];
#pragma unroll
            for (int half = 0; half < 2; half++) {
                int r = r0 + half * 8;
                float v0 = a[half * 2 + 0], v1 = a[half * 2 + 1];
                size_t o = (size_t)r * ldc + cc;
                if (EPI == 0) {
                    *(float2*)&C[o] = make_float2(v0, v1);
                } else if (EPI == 1) {
                    if (cc < N) { atomicAdd(&C[o], v0); atomicAdd(&C[o + 1], v1); }
                } else {
                    float b0 = aux[cc], b1 = aux[cc + 1];
                    float s0 = v0 + b0, s1 = v1 + b1;
                    s0 = (s0 > 20.f) ? s0 : log1pf(__expf(s0));
                    s1 = (s1 > 20.f) ? s1 : log1pf(__expf(s1));
                    *(float2*)&C[o] = make_float2(s0, s1);
                }
            }
        }
    }
}

// ---------------------------------------------------------------------------
// Depthwise causal conv (width 4) + bias + SiLU -> u (f32, scan) + uh (fp16, GEMM)
// ---------------------------------------------------------------------------
__global__ void conv_silu_kernel(const float* __restrict__ xz,
                                 const float* __restrict__ cw,
                                 const float* __restrict__ cb,
                                 float* __restrict__ u,
                                 __half* __restrict__ uh)
{
    int idx = blockIdx.x * blockDim.x + threadIdx.x;
    if (idx >= MROWS * (DI_ / 4)) return;
    int i4 = idx % (DI_ / 4);
    int bt = idx / (DI_ / 4);
    int t  = bt % T_;
    int i  = i4 * 4;

    float4 w0 = ((const float4*)cw)[i + 0];
    float4 w1 = ((const float4*)cw)[i + 1];
    float4 w2 = ((const float4*)cw)[i + 2];
    float4 w3 = ((const float4*)cw)[i + 3];
    float4 bb = ((const float4*)cb)[i4];

    float4 x3 = (t >= 3) ? *(const float4*)&xz[(size_t)(bt - 3) * (2 * DI_) + i] : make_float4(0, 0, 0, 0);
    float4 x2 = (t >= 2) ? *(const float4*)&xz[(size_t)(bt - 2) * (2 * DI_) + i] : make_float4(0, 0, 0, 0);
    float4 x1 = (t >= 1) ? *(const float4*)&xz[(size_t)(bt - 1) * (2 * DI_) + i] : make_float4(0, 0, 0, 0);
    float4 x0 = *(const float4*)&xz[(size_t)bt * (2 * DI_) + i];

    float4 r;
    r.x = bb.x + w0.x * x3.x + w0.y * x2.x + w0.z * x1.x + w0.w * x0.x;
    r.y = bb.y + w1.x * x3.y + w1.y * x2.y + w1.z * x1.y + w1.w * x0.y;
    r.z = bb.z + w2.x * x3.z + w2.y * x2.z + w2.z * x1.z + w2.w * x0.z;
    r.w = bb.w + w3.x * x3.w + w3.y * x2.w + w3.z * x1.w + w3.w * x0.w;

    r.x = r.x / (1.f + __expf(-r.x));
    r.y = r.y / (1.f + __expf(-r.y));
    r.z = r.z / (1.f + __expf(-r.z));
    r.w = r.w / (1.f + __expf(-r.w));

    ((float4*)u)[idx] = r;
    ((uint2*)uh)[idx] = h4(r);
}

// ---------------------------------------------------------------------------
// Selective scan: smem chunk staging with cp.async double buffering.
// Block = 16 channels x 16 states (256 thr). Chunks of 64 timesteps.
// Writes y fp16 (only consumed by out_proj GEMM).
// ---------------------------------------------------------------------------
#define SCH 64
#define NCHK (T_ / SCH)

__global__ void __launch_bounds__(256)
scan_kernel(const float* __restrict__ delta,
            const float* __restrict__ u,
            const float* __restrict__ xdbc,
            const float* __restrict__ xz,
            const float* __restrict__ A_log,
            const float* __restrict__ Dp,
            __half* __restrict__ y)
{
    int b  = blockIdx.x >> 7;
    int ib = blockIdx.x & 127;
    int i0 = ib * 16;
    int tid = threadIdx.x;
    int ci = tid >> 4;
    int s  = tid & 15;
    int i  = i0 + ci;

    __shared__ float sd[2][SCH][16];
    __shared__ float su[2][SCH][16];
    __shared__ float sB[2][SCH][16];
    __shared__ float sC[2][SCH][16];
    __shared__ float sz[2][SCH][16];
    __shared__ float sy[SCH][16];

    float a  = -__expf(A_log[i * DS_ + s]);
    float dp = Dp[i];
    float h  = 0.f;

    int lr = tid >> 2, lc = (tid & 3) * 4;

    auto load_chunk = [&](int stg, int t0) {
        size_t bt = (size_t)(b * T_ + t0 + lr);
        cp16(smem_u32(&sd[stg][lr][lc]), delta + bt * DI_ + i0 + lc, 16);
        cp16(smem_u32(&su[stg][lr][lc]), u + bt * DI_ + i0 + lc, 16);
        cp16(smem_u32(&sB[stg][lr][lc]), xdbc + bt * XDBC_ + R_ + lc, 16);
        cp16(smem_u32(&sC[stg][lr][lc]), xdbc + bt * XDBC_ + R_ + DS_ + lc, 16);
        cp16(smem_u32(&sz[stg][lr][lc]), xz + bt * (2 * DI_) + DI_ + i0 + lc, 16);
        cp_commit();
    };

    load_chunk(0, 0);

    for (int c = 0; c < NCHK; c++) {
        bool hasNext = (c + 1 < NCHK);
        if (hasNext) load_chunk((c + 1) & 1, (c + 1) * SCH);
        if (hasNext) cp_wait<1>(); else cp_wait<0>();
        __syncthreads();

        int stg = c & 1;
#pragma unroll 4
        for (int t = 0; t < SCH; t++) {
            float d  = sd[stg][t][ci];
            float uu = su[stg][t][ci];
            float Bv = sB[stg][t][s];
            float Cv = sC[stg][t][s];
            h = __expf(d * a) * h + (d * uu) * Bv;
            float p = h * Cv;
            p += __shfl_xor_sync(0xffffffffu, p, 8, 16);
            p += __shfl_xor_sync(0xffffffffu, p, 4, 16);
            p += __shfl_xor_sync(0xffffffffu, p, 2, 16);
            p += __shfl_xor_sync(0xffffffffu, p, 1, 16);
            if (s == 0) {
                float z = sz[stg][t][ci];
                sy[t][ci] = (p + uu * dp) * (z / (1.f + __expf(-z)));
            }
        }
        __syncthreads();

        {
            size_t bt = (size_t)(b * T_ + c * SCH + lr);
            float4 v = *(float4*)&sy[lr][lc];
            *(uint2*)(y + bt * DI_ + i0 + lc) = h4(v);
        }
        __syncthreads();
    }
}

// ---------------------------------------------------------------------------
// Launch
// ---------------------------------------------------------------------------
extern "C" void kernel_launch(void* const* d_in, const int* in_sizes, int n_in,
                              void* d_out, int out_size)
{
    const float* x          = (const float*)d_in[0];
    const float* norm_w     = (const float*)d_in[1];
    const float* in_proj_w  = (const float*)d_in[2];
    const float* conv_w     = (const float*)d_in[3];
    const float* conv_b     = (const float*)d_in[4];
    const float* x_proj_w   = (const float*)d_in[5];
    const float* dt_proj_w  = (const float*)d_in[6];
    const float* dt_proj_b  = (const float*)d_in[7];
    const float* A_log      = (const float*)d_in[8];
    const float* D_param    = (const float*)d_in[9];
    const float* out_proj_w = (const float*)d_in[10];
    float* out = (float*)d_out;

    float *xz, *u, *xdbc, *delta;
    __half *xnh, *uh, *yh, *xdbch, *winh, *wouth, *wxph, *wdth;
    cudaGetSymbolAddress((void**)&xz,    g_xz);
    cudaGetSymbolAddress((void**)&u,     g_u);
    cudaGetSymbolAddress((void**)&xdbc,  g_xdbc);
    cudaGetSymbolAddress((void**)&delta, g_delta);
    cudaGetSymbolAddress((void**)&xnh,   g_xnh);
    cudaGetSymbolAddress((void**)&uh,    g_uh);
    cudaGetSymbolAddress((void**)&yh,    g_yh);
    cudaGetSymbolAddress((void**)&xdbch, g_xdbch);
    cudaGetSymbolAddress((void**)&winh,  g_winh);
    cudaGetSymbolAddress((void**)&wouth, g_wouth);
    cudaGetSymbolAddress((void**)&wxph,  g_wxph);
    cudaGetSymbolAddress((void**)&wdth,  g_wdth);

    cudaFuncSetAttribute(gemm_fp16_kernel<0>, cudaFuncAttributeMaxDynamicSharedMemorySize, GSM);
    cudaFuncSetAttribute(gemm_fp16_kernel<1>, cudaFuncAttributeMaxDynamicSharedMemorySize, GSM);
    cudaFuncSetAttribute(gemm_fp16_kernel<3>, cudaFuncAttributeMaxDynamicSharedMemorySize, GSM);

    // #0: convert weights to fp16
    {
        int total = S0_ + S1_ + S2_ + S3_;
        cvt_weights_kernel<<<(total + 255) / 256, 256>>>(
            in_proj_w, winh, out_proj_w, wouth, x_proj_w, wxph, dt_proj_w, wdth);
    }

    // #1: RMSNorm -> xnh
    rmsnorm_kernel<<<MROWS, 256>>>(x, norm_w, xnh);

    // #2: prefill out with residual
    copy_kernel<<<(MROWS * D_ / 4 + 255) / 256, 256>>>(x, out, MROWS * D_ / 4);

    // #3: in_proj: xz[2048,4096] = xn @ W^T   (512 CTAs)  <-- ncu captures this
    gemm_fp16_kernel<0><<<dim3(2 * DI_ / 128, MROWS / 128, 1), 256, GSM>>>(
        xnh, D_, winh, D_, nullptr, xz, 2 * DI_, 2 * DI_, D_);

    // #4: conv + silu -> u (f32) + uh (fp16)
    conv_silu_kernel<<<(MROWS * DI_ / 4 + 255) / 256, 256>>>(xz, conv_w, conv_b, u, uh);

    // #5: x_proj: xdbc = u @ W^T (split-K=8, atomics; 128 CTAs)
    cudaMemsetAsync(xdbc, 0, (size_t)MROWS * XDBC_ * sizeof(float));
    gemm_fp16_kernel<1><<<dim3(1, MROWS / 128, 8), 256, GSM>>>(
        uh, DI_, wxph, DI_, nullptr, xdbc, XDBC_, XDBC_, DI_ / 8);

    // #6: xdbc -> fp16 for dt_proj
    cvt_kernel<<<(MROWS * XDBC_ / 4 + 255) / 256, 256>>>(xdbc, xdbch, MROWS * XDBC_ / 4);

    // #7: dt_proj + softplus: delta[2048,2048] (K=64, single chunk; 256 CTAs)
    gemm_fp16_kernel<3><<<dim3(DI_ / 128, MROWS / 128, 1), 256, GSM>>>(
        xdbch, XDBC_, wdth, R_, dt_proj_b, delta, DI_, DI_, R_);

    // #8: selective scan (fused gate + skip) -> yh
    scan_kernel<<<B_ * (DI_ / 16), 256>>>(delta, u, xdbc, xz, A_log, D_param, yh);

    // #9: out_proj + residual: split-K=2 atomicAdd into prefilled out (256 CTAs)
    gemm_fp16_kernel<1><<<dim3(D_ / 128, MROWS / 128, 2), 256, GSM>>>(
        yh, DI_, wouth, DI_, nullptr, out, D_, D_, DI_ / 2);
}

// round 13
// speedup vs baseline: 4.5933x; 1.0150x over previous
#include <cuda_runtime.h>
#include <cuda_fp16.h>
#include <math.h>
#include <stdint.h>

// Problem dims
#define B_   2
#define T_   1024
#define D_   1024
#define DI_  2048          // D_INNER
#define DS_  16            // D_STATE
#define R_   64            // DT_RANK
#define XDBC_ 96           // R_ + 2*DS_
#define MROWS (B_*T_)      // 2048

// ---------------------------------------------------------------------------
// Scratch (device globals; no allocation allowed)
// ---------------------------------------------------------------------------
__device__ __align__(256) float g_xz[MROWS * 2 * DI_];     // in_proj out (f32)
__device__ __align__(256) float g_u[MROWS * DI_];          // conv out f32 (scan)
__device__ __align__(256) float g_xdbc[MROWS * XDBC_];     // x_proj out (f32)
__device__ __align__(256) float g_delta[MROWS * DI_];      // dt_proj out (f32)

__device__ __align__(256) __half g_xnh[MROWS * D_];        // rmsnorm out
__device__ __align__(256) __half g_uh[MROWS * DI_];        // conv out (GEMM input)
__device__ __align__(256) __half g_yh[MROWS * DI_];        // scan out
__device__ __align__(256) __half g_xdbch[MROWS * XDBC_];   // xdbc (dt_proj input)
__device__ __align__(256) __half g_winh[2 * DI_ * D_];
__device__ __align__(256) __half g_wouth[D_ * DI_];
__device__ __align__(256) __half g_wxph[XDBC_ * DI_];
__device__ __align__(256) __half g_wdth[DI_ * R_];

// ---------------------------------------------------------------------------
// Helpers
// ---------------------------------------------------------------------------
__device__ __forceinline__ uint32_t smem_u32(const void* p) {
    uint32_t a;
    asm("{ .reg .u64 t; cvta.to.shared.u64 t, %1; cvt.u32.u64 %0, t; }" : "=r"(a) : "l"(p));
    return a;
}
__device__ __forceinline__ uint32_t sw128(uint32_t b) { return b ^ ((b >> 3) & 0x70); }

__device__ __forceinline__ void cp16(uint32_t smem, const void* gmem, int srcBytes) {
    asm volatile("cp.async.cg.shared.global [%0], [%1], 16, %2;"
                 :: "r"(smem), "l"(gmem), "r"(srcBytes));
}
__device__ __forceinline__ void cp_commit() {
    asm volatile("cp.async.commit_group;" ::: "memory");
}
template<int N>
__device__ __forceinline__ void cp_wait() {
    asm volatile("cp.async.wait_group %0;" :: "n"(N) : "memory");
}

__device__ __forceinline__ void ldsm_x4(uint32_t* r, uint32_t addr) {
    asm volatile("ldmatrix.sync.aligned.m8n8.x4.shared.b16 {%0,%1,%2,%3}, [%4];"
                 : "=r"(r[0]), "=r"(r[1]), "=r"(r[2]), "=r"(r[3]) : "r"(addr));
}
// fp16 m16n8k16 MMA, f32 accumulate
__device__ __forceinline__ void mma_fp16(float* c, const uint32_t* a, const uint32_t* b) {
    asm volatile("mma.sync.aligned.m16n8k16.row.col.f32.f16.f16.f32 "
                 "{%0,%1,%2,%3}, {%4,%5,%6,%7}, {%8,%9}, {%0,%1,%2,%3};"
                 : "+f"(c[0]), "+f"(c[1]), "+f"(c[2]), "+f"(c[3])
                 : "r"(a[0]), "r"(a[1]), "r"(a[2]), "r"(a[3]), "r"(b[0]), "r"(b[1]));
}

// pack 4 f32 -> 4 fp16 (uint2)
__device__ __forceinline__ uint2 h4(float4 v) {
    __half2 a = __floats2half2_rn(v.x, v.y);
    __half2 b = __floats2half2_rn(v.z, v.w);
    return make_uint2(*(uint32_t*)&a, *(uint32_t*)&b);
}

// ---------------------------------------------------------------------------
// Convert all weights to fp16 (fused, float4-vectorized)
// ---------------------------------------------------------------------------
#define S0_ (2 * DI_ * D_ / 4)
#define S1_ (D_ * DI_ / 4)
#define S2_ (XDBC_ * DI_ / 4)
#define S3_ (DI_ * R_ / 4)

__global__ void cvt_weights_kernel(
    const float* __restrict__ w0, __half* __restrict__ o0,
    const float* __restrict__ w1, __half* __restrict__ o1,
    const float* __restrict__ w2, __half* __restrict__ o2,
    const float* __restrict__ w3, __half* __restrict__ o3)
{
    int i = blockIdx.x * blockDim.x + threadIdx.x;
    const float* src; __half* dst; int off;
    if (i < S0_)                        { src = w0; dst = o0; off = i; }
    else if (i < S0_ + S1_)             { src = w1; dst = o1; off = i - S0_; }
    else if (i < S0_ + S1_ + S2_)       { src = w2; dst = o2; off = i - S0_ - S1_; }
    else if (i < S0_ + S1_ + S2_ + S3_) { src = w3; dst = o3; off = i - S0_ - S1_ - S2_; }
    else return;
    ((uint2*)dst)[off] = h4(((const float4*)src)[off]);
}

__global__ void cvt_kernel(const float* __restrict__ src, __half* __restrict__ dst, int n4)
{
    int i = blockIdx.x * blockDim.x + threadIdx.x;
    if (i < n4) ((uint2*)dst)[i] = h4(((const float4*)src)[i]);
}

__global__ void copy_kernel(const float* __restrict__ src, float* __restrict__ dst, int n4)
{
    int i = blockIdx.x * blockDim.x + threadIdx.x;
    if (i < n4) ((float4*)dst)[i] = ((const float4*)src)[i];
}

// ---------------------------------------------------------------------------
// RMSNorm -> fp16
// ---------------------------------------------------------------------------
__global__ void rmsnorm_kernel(const float* __restrict__ x,
                               const float* __restrict__ w,
                               __half* __restrict__ o)
{
    int row = blockIdx.x;
    const float* xr = x + (size_t)row * D_;
    float s = 0.f;
    for (int i = threadIdx.x; i < D_ / 4; i += 256) {
        float4 v = ((const float4*)xr)[i];
        s += v.x * v.x + v.y * v.y + v.z * v.z + v.w * v.w;
    }
    __shared__ float red[8];
    for (int off = 16; off; off >>= 1) s += __shfl_xor_sync(0xffffffffu, s, off);
    if ((threadIdx.x & 31) == 0) red[threadIdx.x >> 5] = s;
    __syncthreads();
    if (threadIdx.x < 8) {
        float t = red[threadIdx.x];
        t += __shfl_xor_sync(0xffu, t, 4);
        t += __shfl_xor_sync(0xffu, t, 2);
        t += __shfl_xor_sync(0xffu, t, 1);
        if (threadIdx.x == 0) red[0] = t;
    }
    __syncthreads();
    float scale = rsqrtf(red[0] * (1.f / D_) + 1.1920929e-7f);
    for (int i = threadIdx.x; i < D_ / 4; i += 256) {
        float4 v = ((const float4*)xr)[i];
        float4 wv = ((const float4*)w)[i];
        v.x *= scale * wv.x; v.y *= scale * wv.y;
        v.z *= scale * wv.z; v.w *= scale * wv.w;
        ((uint2*)(o + (size_t)row * D_))[i] = h4(v);
    }
}

// ---------------------------------------------------------------------------
// fp16 tensor-core GEMM (fragment-pipelined):
//   C[M, N(ldc)] (op)= A[M,*](lda) @ W[N,*](ldb)^T over K slice [z*kLen, +kLen)
// 128x128 CTA tile, BK=64, 256 threads (8 warps 2x4), warp tile 64x32.
// 3-stage cp.async pipeline; 1 __syncthreads per chunk; LDSM/MMA overlapped.
// EPI: 0 = store, 1 = atomicAdd (split-K), 3 = softplus(v + bias[n])
// ---------------------------------------------------------------------------
#define GSTG 32768
#define GSM  (3 * GSTG)

template<int EPI>
__global__ void __launch_bounds__(256, 2)
gemm_fp16_kernel(const __half* __restrict__ A, int lda,
                 const __half* __restrict__ Bm, int ldb,
                 const float* __restrict__ aux, float* __restrict__ C,
                 int N, int ldc, int kLen)
{
    extern __shared__ char smem[];
    uint32_t sb = smem_u32(smem);
    int tid = threadIdx.x, wid = tid >> 5, lid = tid & 31;
    int m0 = blockIdx.y * 128, n0 = blockIdx.x * 128;
    int kStart = blockIdx.z * kLen;
    int bRows = N - n0; if (bRows > 128) bRows = 128;
    int wm = (wid >> 2) * 64, wn = (wid & 3) * 32;

    float acc[4][4][4];
#pragma unroll
    for (int i = 0; i < 4; i++)
#pragma unroll
        for (int j = 0; j < 4; j++)
#pragma unroll
            for (int k = 0; k < 4; k++) acc[i][j][k] = 0.f;

    int nCh = kLen / 64;

    auto load_chunk = [&](int s, int k0) {
        uint32_t st = sb + s * GSTG;
#pragma unroll
        for (int p = 0; p < 4; p++) {
            int idx = tid + p * 256;
            int r = idx >> 3, c = idx & 7;
            uint32_t so = sw128((uint32_t)(r * 128 + c * 16));
            cp16(st + so, A + (size_t)(m0 + r) * lda + k0 + c * 8, 16);
        }
#pragma unroll
        for (int p = 0; p < 4; p++) {
            int idx = tid + p * 256;
            int r = idx >> 3, c = idx & 7;
            uint32_t so = sw128((uint32_t)(r * 128 + c * 16));
            int rb = (r < bRows) ? r : (bRows - 1);
            int ok = (r < bRows) ? 16 : 0;
            cp16(st + 16384 + so, Bm + (size_t)(n0 + rb) * ldb + k0 + c * 8, ok);
        }
        cp_commit();
    };

    // fragment loaders
    auto load_af = [&](uint32_t (*af)[4], uint32_t stA, int ks) {
#pragma unroll
        for (int mt = 0; mt < 4; mt++) {
            int row = wm + mt * 16 + (lid & 15);
            int chunk = ks * 2 + (lid >> 4);
            ldsm_x4(af[mt], stA + sw128((uint32_t)(row * 128 + chunk * 16)));
        }
    };
    auto load_bf = [&](uint32_t (*bf)[4], uint32_t stB, int cb) {
#pragma unroll
        for (int nt = 0; nt < 4; nt++) {
            int row = wn + nt * 8 + (lid & 7);
            int chunk = cb + (lid >> 3);
            ldsm_x4(bf[nt], stB + sw128((uint32_t)(row * 128 + chunk * 16)));
        }
    };
    auto mma_step = [&](uint32_t (*af)[4], uint32_t (*bf)[4], int half) {
#pragma unroll
        for (int mt = 0; mt < 4; mt++)
#pragma unroll
            for (int nt = 0; nt < 4; nt++)
                mma_fp16(acc[mt][nt], af[mt], bf[nt] + half * 2);
    };

    load_chunk(0, kStart);
    if (nCh > 1) load_chunk(1, kStart + 64);

    int stg = 0;
    for (int ch = 0; ch < nCh; ch++) {
        if (ch + 1 < nCh) cp_wait<1>(); else cp_wait<0>();
        __syncthreads();
        if (ch + 2 < nCh) {
            int s2 = stg + 2; if (s2 >= 3) s2 -= 3;
            load_chunk(s2, kStart + (ch + 2) * 64);
        }

        uint32_t stA = sb + stg * GSTG;
        uint32_t stB = stA + 16384;

        uint32_t af0[4][4], af1[4][4], bf[4][4];
        load_bf(bf, stB, 0);         // pair 0 (k16 steps 0,1)
        load_af(af0, stA, 0);
        load_af(af1, stA, 1);
        mma_step(af0, bf, 0);        // ks0
        load_af(af0, stA, 2);        // prefetch ks2
        mma_step(af1, bf, 1);        // ks1
        load_bf(bf, stB, 4);         // pair 1 (k16 steps 2,3)
        load_af(af1, stA, 3);        // prefetch ks3
        mma_step(af0, bf, 0);        // ks2
        mma_step(af1, bf, 1);        // ks3

        if (++stg == 3) stg = 0;
    }

    int gid = lid >> 2, tig = lid & 3;
#pragma unroll
    for (int mt = 0; mt < 4; mt++) {
        int r0 = m0 + wm + mt * 16 + gid;
#pragma unroll
        for (int nt = 0; nt < 4; nt++) {
            int cc = n0 + wn + nt * 8 + tig * 2;
            float* a = acc[mt][nt];
#pragma unroll
            for (int half = 0; half < 2; half++) {
                int r = r0 + half * 8;
                float v0 = a[half * 2 + 0], v1 = a[half * 2 + 1];
                size_t o = (size_t)r * ldc + cc;
                if (EPI == 0) {
                    *(float2*)&C[o] = make_float2(v0, v1);
                } else if (EPI == 1) {
                    if (cc < N) { atomicAdd(&C[o], v0); atomicAdd(&C[o + 1], v1); }
                } else {
                    float b0 = aux[cc], b1 = aux[cc + 1];
                    float s0 = v0 + b0, s1 = v1 + b1;
                    s0 = (s0 > 20.f) ? s0 : log1pf(__expf(s0));
                    s1 = (s1 > 20.f) ? s1 : log1pf(__expf(s1));
                    *(float2*)&C[o] = make_float2(s0, s1);
                }
            }
        }
    }
}

// ---------------------------------------------------------------------------
// Depthwise causal conv (width 4) + bias + SiLU -> u (f32, scan) + uh (fp16, GEMM)
// ---------------------------------------------------------------------------
__global__ void conv_silu_kernel(const float* __restrict__ xz,
                                 const float* __restrict__ cw,
                                 const float* __restrict__ cb,
                                 float* __restrict__ u,
                                 __half* __restrict__ uh)
{
    int idx = blockIdx.x * blockDim.x + threadIdx.x;
    if (idx >= MROWS * (DI_ / 4)) return;
    int i4 = idx % (DI_ / 4);
    int bt = idx / (DI_ / 4);
    int t  = bt % T_;
    int i  = i4 * 4;

    float4 w0 = ((const float4*)cw)[i + 0];
    float4 w1 = ((const float4*)cw)[i + 1];
    float4 w2 = ((const float4*)cw)[i + 2];
    float4 w3 = ((const float4*)cw)[i + 3];
    float4 bb = ((const float4*)cb)[i4];

    float4 x3 = (t >= 3) ? *(const float4*)&xz[(size_t)(bt - 3) * (2 * DI_) + i] : make_float4(0, 0, 0, 0);
    float4 x2 = (t >= 2) ? *(const float4*)&xz[(size_t)(bt - 2) * (2 * DI_) + i] : make_float4(0, 0, 0, 0);
    float4 x1 = (t >= 1) ? *(const float4*)&xz[(size_t)(bt - 1) * (2 * DI_) + i] : make_float4(0, 0, 0, 0);
    float4 x0 = *(const float4*)&xz[(size_t)bt * (2 * DI_) + i];

    float4 r;
    r.x = bb.x + w0.x * x3.x + w0.y * x2.x + w0.z * x1.x + w0.w * x0.x;
    r.y = bb.y + w1.x * x3.y + w1.y * x2.y + w1.z * x1.y + w1.w * x0.y;
    r.z = bb.z + w2.x * x3.z + w2.y * x2.z + w2.z * x1.z + w2.w * x0.z;
    r.w = bb.w + w3.x * x3.w + w3.y * x2.w + w3.z * x1.w + w3.w * x0.w;

    r.x = r.x / (1.f + __expf(-r.x));
    r.y = r.y / (1.f + __expf(-r.y));
    r.z = r.z / (1.f + __expf(-r.z));
    r.w = r.w / (1.f + __expf(-r.w));

    ((float4*)u)[idx] = r;
    ((uint2*)uh)[idx] = h4(r);
}

// ---------------------------------------------------------------------------
// Selective scan: smem chunk staging with cp.async double buffering.
// Block = 16 channels x 16 states (256 thr). Chunks of 64 timesteps.
// ---------------------------------------------------------------------------
#define SCH 64
#define NCHK (T_ / SCH)

__global__ void __launch_bounds__(256)
scan_kernel(const float* __restrict__ delta,
            const float* __restrict__ u,
            const float* __restrict__ xdbc,
            const float* __restrict__ xz,
            const float* __restrict__ A_log,
            const float* __restrict__ Dp,
            __half* __restrict__ y)
{
    int b  = blockIdx.x >> 7;
    int ib = blockIdx.x & 127;
    int i0 = ib * 16;
    int tid = threadIdx.x;
    int ci = tid >> 4;
    int s  = tid & 15;
    int i  = i0 + ci;

    __shared__ float sd[2][SCH][16];
    __shared__ float su[2][SCH][16];
    __shared__ float sB[2][SCH][16];
    __shared__ float sC[2][SCH][16];
    __shared__ float sz[2][SCH][16];
    __shared__ float sy[SCH][16];

    float a  = -__expf(A_log[i * DS_ + s]);
    float dp = Dp[i];
    float h  = 0.f;

    int lr = tid >> 2, lc = (tid & 3) * 4;

    auto load_chunk = [&](int stg, int t0) {
        size_t bt = (size_t)(b * T_ + t0 + lr);
        cp16(smem_u32(&sd[stg][lr][lc]), delta + bt * DI_ + i0 + lc, 16);
        cp16(smem_u32(&su[stg][lr][lc]), u + bt * DI_ + i0 + lc, 16);
        cp16(smem_u32(&sB[stg][lr][lc]), xdbc + bt * XDBC_ + R_ + lc, 16);
        cp16(smem_u32(&sC[stg][lr][lc]), xdbc + bt * XDBC_ + R_ + DS_ + lc, 16);
        cp16(smem_u32(&sz[stg][lr][lc]), xz + bt * (2 * DI_) + DI_ + i0 + lc, 16);
        cp_commit();
    };

    load_chunk(0, 0);

    for (int c = 0; c < NCHK; c++) {
        bool hasNext = (c + 1 < NCHK);
        if (hasNext) load_chunk((c + 1) & 1, (c + 1) * SCH);
        if (hasNext) cp_wait<1>(); else cp_wait<0>();
        __syncthreads();

        int stg = c & 1;
#pragma unroll 4
        for (int t = 0; t < SCH; t++) {
            float d  = sd[stg][t][ci];
            float uu = su[stg][t][ci];
            float Bv = sB[stg][t][s];
            float Cv = sC[stg][t][s];
            h = __expf(d * a) * h + (d * uu) * Bv;
            float p = h * Cv;
            p += __shfl_xor_sync(0xffffffffu, p, 8, 16);
            p += __shfl_xor_sync(0xffffffffu, p, 4, 16);
            p += __shfl_xor_sync(0xffffffffu, p, 2, 16);
            p += __shfl_xor_sync(0xffffffffu, p, 1, 16);
            if (s == 0) {
                float z = sz[stg][t][ci];
                sy[t][ci] = (p + uu * dp) * (z / (1.f + __expf(-z)));
            }
        }
        __syncthreads();

        {
            size_t bt = (size_t)(b * T_ + c * SCH + lr);
            float4 v = *(float4*)&sy[lr][lc];
            *(uint2*)(y + bt * DI_ + i0 + lc) = h4(v);
        }
        __syncthreads();
    }
}

// ---------------------------------------------------------------------------
// Launch
// ---------------------------------------------------------------------------
extern "C" void kernel_launch(void* const* d_in, const int* in_sizes, int n_in,
                              void* d_out, int out_size)
{
    const float* x          = (const float*)d_in[0];
    const float* norm_w     = (const float*)d_in[1];
    const float* in_proj_w  = (const float*)d_in[2];
    const float* conv_w     = (const float*)d_in[3];
    const float* conv_b     = (const float*)d_in[4];
    const float* x_proj_w   = (const float*)d_in[5];
    const float* dt_proj_w  = (const float*)d_in[6];
    const float* dt_proj_b  = (const float*)d_in[7];
    const float* A_log      = (const float*)d_in[8];
    const float* D_param    = (const float*)d_in[9];
    const float* out_proj_w = (const float*)d_in[10];
    float* out = (float*)d_out;

    float *xz, *u, *xdbc, *delta;
    __half *xnh, *uh, *yh, *xdbch, *winh, *wouth, *wxph, *wdth;
    cudaGetSymbolAddress((void**)&xz,    g_xz);
    cudaGetSymbolAddress((void**)&u,     g_u);
    cudaGetSymbolAddress((void**)&xdbc,  g_xdbc);
    cudaGetSymbolAddress((void**)&delta, g_delta);
    cudaGetSymbolAddress((void**)&xnh,   g_xnh);
    cudaGetSymbolAddress((void**)&uh,    g_uh);
    cudaGetSymbolAddress((void**)&yh,    g_yh);
    cudaGetSymbolAddress((void**)&xdbch, g_xdbch);
    cudaGetSymbolAddress((void**)&winh,  g_winh);
    cudaGetSymbolAddress((void**)&wouth, g_wouth);
    cudaGetSymbolAddress((void**)&wxph,  g_wxph);
    cudaGetSymbolAddress((void**)&wdth,  g_wdth);

    cudaFuncSetAttribute(gemm_fp16_kernel<0>, cudaFuncAttributeMaxDynamicSharedMemorySize, GSM);
    cudaFuncSetAttribute(gemm_fp16_kernel<1>, cudaFuncAttributeMaxDynamicSharedMemorySize, GSM);
    cudaFuncSetAttribute(gemm_fp16_kernel<3>, cudaFuncAttributeMaxDynamicSharedMemorySize, GSM);

    // #0: convert weights to fp16
    {
        int total = S0_ + S1_ + S2_ + S3_;
        cvt_weights_kernel<<<(total + 255) / 256, 256>>>(
            in_proj_w, winh, out_proj_w, wouth, x_proj_w, wxph, dt_proj_w, wdth);
    }

    // #1: RMSNorm -> xnh
    rmsnorm_kernel<<<MROWS, 256>>>(x, norm_w, xnh);

    // #2: prefill out with residual
    copy_kernel<<<(MROWS * D_ / 4 + 255) / 256, 256>>>(x, out, MROWS * D_ / 4);

    // #3: in_proj: xz[2048,4096] = xn @ W^T   (512 CTAs)  <-- ncu captures this
    gemm_fp16_kernel<0><<<dim3(2 * DI_ / 128, MROWS / 128, 1), 256, GSM>>>(
        xnh, D_, winh, D_, nullptr, xz, 2 * DI_, 2 * DI_, D_);

    // #4: conv + silu -> u (f32) + uh (fp16)
    conv_silu_kernel<<<(MROWS * DI_ / 4 + 255) / 256, 256>>>(xz, conv_w, conv_b, u, uh);

    // #5: x_proj: xdbc = u @ W^T (split-K=8, atomics; 128 CTAs)
    cudaMemsetAsync(xdbc, 0, (size_t)MROWS * XDBC_ * sizeof(float));
    gemm_fp16_kernel<1><<<dim3(1, MROWS / 128, 8), 256, GSM>>>(
        uh, DI_, wxph, DI_, nullptr, xdbc, XDBC_, XDBC_, DI_ / 8);

    // #6: xdbc -> fp16 for dt_proj
    cvt_kernel<<<(MROWS * XDBC_ / 4 + 255) / 256, 256>>>(xdbc, xdbch, MROWS * XDBC_ / 4);

    // #7: dt_proj + softplus: delta[2048,2048] (K=64, single chunk; 256 CTAs)
    gemm_fp16_kernel<3><<<dim3(DI_ / 128, MROWS / 128, 1), 256, GSM>>>(
        xdbch, XDBC_, wdth, R_, dt_proj_b, delta, DI_, DI_, R_);

    // #8: selective scan (fused gate + skip) -> yh
    scan_kernel<<<B_ * (DI_ / 16), 256>>>(delta, u, xdbc, xz, A_log, D_param, yh);

    // #9: out_proj + residual: split-K=2 atomicAdd into prefilled out (256 CTAs)
    gemm_fp16_kernel<1><<<dim3(D_ / 128, MROWS / 128, 2), 256, GSM>>>(
        yh, DI_, wouth, DI_, nullptr, out, D_, D_, DI_ / 2);
}